// round 2
// baseline (speedup 1.0000x reference)
#include <cuda_runtime.h>
#include <math.h>

#define CN1 10000
#define CN2 10000
#define CF_IN 256
#define CHID 128
#define CNH 8
#define CDH 16
#define CNL 2

// ---------------- scratch (static device globals; no allocation) ----------------
__device__ float g_h1[CN1 * CHID];
__device__ float g_h2[CN2 * CHID];
__device__ float g_q1[CN1 * CHID], g_kt1[CN1 * CHID], g_vt1[CN1 * CHID];
__device__ float g_q2[CN2 * CHID], g_kt2[CN2 * CHID], g_vt2[CN2 * CHID];
__device__ float g_agg1[CN1 * CHID], g_agg2[CN2 * CHID];
__device__ float g_s1[CN1 * CNH], g_s2[CN2 * CNH];
__device__ float g_Em[CN1 * CHID * CNL], g_Ed[CN2 * CHID * CNL];
__device__ float g_Wkp[CNL * 2 * CHID * CHID], g_bkp[CNL * 2 * CHID];
__device__ float g_Wvp[CNL * 2 * CHID * CHID], g_bvp[CNL * 2 * CHID];

// ---------------- helpers ----------------
__device__ __forceinline__ float gelu_f(float x) {
    // jax.nn.gelu default (approximate=True, tanh form)
    float x3 = x * x * x;
    return 0.5f * x * (1.0f + tanhf(0.7978845608028654f * (x + 0.044715f * x3)));
}

__device__ __forceinline__ void red_add4(float* p, float a, float b, float c, float d) {
    asm volatile("red.global.add.v4.f32 [%0], {%1,%2,%3,%4};"
                 :: "l"(p), "f"(a), "f"(b), "f"(c), "f"(d) : "memory");
}

// ---------------- fold arel/mrel into Wk/Wv ----------------
// Wp[c, h*16+e] = sum_d W[c, h*16+d] * rel[h, d, e]; same for bias.
__global__ void prep_weights(const float* __restrict__ Wk, const float* __restrict__ bk,
                             const float* __restrict__ Wv, const float* __restrict__ bv,
                             const float* __restrict__ arel, const float* __restrict__ mrel) {
    int combo = blockIdx.x;   // l*2+t, 0..3
    int which = blockIdx.y;   // 0 -> (Wk, arel), 1 -> (Wv, mrel)
    const float* W   = (which ? Wv : Wk) + combo * CHID * CHID;
    const float* bb  = (which ? bv : bk) + combo * CHID;
    const float* rel = (which ? mrel : arel) + combo * CNH * CDH * CDH;
    float* Wp = (which ? g_Wvp : g_Wkp) + combo * CHID * CHID;
    float* bp = (which ? g_bvp : g_bkp) + combo * CHID;

    int tid = threadIdx.x;
    for (int i = tid; i < CHID * CHID; i += blockDim.x) {
        int c = i >> 7, col = i & 127, h = col >> 4, e = col & 15;
        float acc = 0.f;
#pragma unroll
        for (int d = 0; d < CDH; d++)
            acc += W[c * CHID + h * CDH + d] * rel[h * CDH * CDH + d * CDH + e];
        Wp[i] = acc;
    }
    if (tid < CHID) {
        int h = tid >> 4, e = tid & 15;
        float acc = 0.f;
#pragma unroll
        for (int d = 0; d < CDH; d++)
            acc += bb[h * CDH + d] * rel[h * CDH * CDH + d * CDH + e];
        bp[tid] = acc;
    }
}

// ---------------- zero accumulators ----------------
__global__ void zero_bufs() {
    int tid = blockIdx.x * blockDim.x + threadIdx.x;
    if (tid < CN1 * CHID) { g_agg1[tid] = 0.f; g_agg2[tid] = 0.f; }
    if (tid < CN1 * CNH)  { g_s1[tid] = 0.f;  g_s2[tid] = 0.f; }
}

// ---------------- generic [M,K]@[K,128] GEMM ----------------
// mode 0: C = A@B + bias
// mode 1: C = relu(A@B + bias)
// mode 2: A' = gelu(A / (sdiv + 1e-16)) ; C = sg*(A'@B + bias) + (1-sg)*hold,  sg = sigmoid(*skipp)
__global__ void __launch_bounds__(128)
gemm128(const float* __restrict__ A, int lda,
        const float* __restrict__ B, const float* __restrict__ bias,
        float* __restrict__ C, int ldc, int M, int K, int mode,
        const float* __restrict__ sdiv,
        const float* __restrict__ hold, int ldh,
        const float* __restrict__ skipp) {
    __shared__ float As[32][68];     // [k][m], padded (68*4 bytes = 16B-aligned rows)
    __shared__ float Bs[32][128];    // [k][n]

    int tid = threadIdx.x;
    int tx = tid & 15;               // 16 column groups of 8
    int ty = tid >> 4;               // 8 row groups of 8
    int m0 = blockIdx.x * 64;

    float acc[8][8];
#pragma unroll
    for (int i = 0; i < 8; i++)
#pragma unroll
        for (int j = 0; j < 8; j++) acc[i][j] = 0.f;

    for (int k0 = 0; k0 < K; k0 += 32) {
        // A tile: 64x32, transposed into As[k][m]; 4 float4 per thread
#pragma unroll
        for (int i = 0; i < 4; i++) {
            int lin = tid + i * 128;
            int row = lin >> 3;
            int kc  = (lin & 7) << 2;
            float4 v = make_float4(0.f, 0.f, 0.f, 0.f);
            int m = m0 + row;
            if (m < M) {
                v = *(const float4*)(A + (size_t)m * lda + k0 + kc);
                if (mode == 2) {
                    float inv = 1.0f / (sdiv[m * CNH + ((k0 + kc) >> 4)] + 1e-16f);
                    v.x = gelu_f(v.x * inv); v.y = gelu_f(v.y * inv);
                    v.z = gelu_f(v.z * inv); v.w = gelu_f(v.w * inv);
                }
            }
            As[kc + 0][row] = v.x; As[kc + 1][row] = v.y;
            As[kc + 2][row] = v.z; As[kc + 3][row] = v.w;
        }
        // B tile: 32x128; 8 float4 per thread
#pragma unroll
        for (int i = 0; i < 8; i++) {
            int lin = tid + i * 128;
            int kr = lin >> 5;
            int nc = (lin & 31) << 2;
            *(float4*)&Bs[kr][nc] = *(const float4*)(B + (size_t)(k0 + kr) * CHID + nc);
        }
        __syncthreads();

#pragma unroll 8
        for (int kk = 0; kk < 32; kk++) {
            float a[8], b[8];
            float4 t0 = *(const float4*)&As[kk][ty * 8];
            float4 t1 = *(const float4*)&As[kk][ty * 8 + 4];
            a[0]=t0.x; a[1]=t0.y; a[2]=t0.z; a[3]=t0.w;
            a[4]=t1.x; a[5]=t1.y; a[6]=t1.z; a[7]=t1.w;
            float4 u0 = *(const float4*)&Bs[kk][tx * 8];
            float4 u1 = *(const float4*)&Bs[kk][tx * 8 + 4];
            b[0]=u0.x; b[1]=u0.y; b[2]=u0.z; b[3]=u0.w;
            b[4]=u1.x; b[5]=u1.y; b[6]=u1.z; b[7]=u1.w;
#pragma unroll
            for (int i = 0; i < 8; i++)
#pragma unroll
                for (int j = 0; j < 8; j++)
                    acc[i][j] += a[i] * b[j];
        }
        __syncthreads();
    }

    float sg = 1.f, sg1 = 0.f;
    if (mode == 2) {
        sg = 1.0f / (1.0f + __expf(-*skipp));
        sg1 = 1.0f - sg;
    }
#pragma unroll
    for (int i = 0; i < 8; i++) {
        int m = m0 + ty * 8 + i;
        if (m < M) {
#pragma unroll
            for (int jj = 0; jj < 2; jj++) {
                int n = tx * 8 + jj * 4;
                float4 r;
                r.x = acc[i][jj * 4 + 0] + bias[n + 0];
                r.y = acc[i][jj * 4 + 1] + bias[n + 1];
                r.z = acc[i][jj * 4 + 2] + bias[n + 2];
                r.w = acc[i][jj * 4 + 3] + bias[n + 3];
                if (mode == 1) {
                    r.x = fmaxf(r.x, 0.f); r.y = fmaxf(r.y, 0.f);
                    r.z = fmaxf(r.z, 0.f); r.w = fmaxf(r.w, 0.f);
                } else if (mode == 2) {
                    const float* hp = hold + (size_t)m * ldh + n;
                    r.x = sg * r.x + sg1 * hp[0];
                    r.y = sg * r.y + sg1 * hp[1];
                    r.z = sg * r.z + sg1 * hp[2];
                    r.w = sg * r.w + sg1 * hp[3];
                }
                *(float4*)(C + (size_t)m * ldc + n) = r;
            }
        }
    }
}

// ---------------- edge attention (one warp per edge) ----------------
// logits[h] = dot(q[dst,h,:], kt[src,h,:]) * prior[h] / 4 ; e = exp(logit)
// s[dst,h] += e ; agg[dst,:] += e * vt[src,:]
__global__ void __launch_bounds__(256)
edge_attend(const int* __restrict__ ei, int E,
            const float* __restrict__ q,
            const float* __restrict__ kt,
            const float* __restrict__ vt,
            const float* __restrict__ prior,
            float* __restrict__ agg,
            float* __restrict__ s) {
    int warp = (blockIdx.x * blockDim.x + threadIdx.x) >> 5;
    int lane = threadIdx.x & 31;
    if (warp >= E) return;
    int src = ei[warp];
    int dst = ei[E + warp];

    const float4 q4 = __ldg((const float4*)(q + (size_t)dst * CHID) + lane);
    const float4 k4 = __ldg((const float4*)(kt + (size_t)src * CHID) + lane);
    float d = q4.x * k4.x + q4.y * k4.y + q4.z * k4.z + q4.w * k4.w;
    d += __shfl_xor_sync(0xffffffffu, d, 1);
    d += __shfl_xor_sync(0xffffffffu, d, 2);
    int h = lane >> 2;
    float e = __expf(d * __ldg(prior + h) * 0.25f);

    if ((lane & 3) == 0)
        atomicAdd(s + (size_t)dst * CNH + h, e);

    const float4 v4 = __ldg((const float4*)(vt + (size_t)src * CHID) + lane);
    red_add4(agg + (size_t)dst * CHID + lane * 4, e * v4.x, e * v4.y, e * v4.z, e * v4.w);
}

// ---------------- final pair scores (one warp per pair) ----------------
__global__ void __launch_bounds__(256)
pred_kernel(const int* __restrict__ pidx, int P, float* __restrict__ out) {
    int warp = (blockIdx.x * blockDim.x + threadIdx.x) >> 5;
    int lane = threadIdx.x & 31;
    if (warp >= P) return;
    int i = pidx[warp];
    int j = pidx[P + warp];
    const float4* em = (const float4*)(g_Em + (size_t)i * (CHID * CNL));
    const float4* ed = (const float4*)(g_Ed + (size_t)j * (CHID * CNL));
    float4 a0 = em[lane],      b0 = ed[lane];
    float4 a1 = em[32 + lane], b1 = ed[32 + lane];
    float d = a0.x * b0.x + a0.y * b0.y + a0.z * b0.z + a0.w * b0.w
            + a1.x * b1.x + a1.y * b1.y + a1.z * b1.z + a1.w * b1.w;
#pragma unroll
    for (int o = 16; o > 0; o >>= 1) d += __shfl_xor_sync(0xffffffffu, d, o);
    if (lane == 0) out[warp] = d;
}

// ---------------- host driver ----------------
extern "C" void kernel_launch(void* const* d_in, const int* in_sizes, int n_in,
                              void* d_out, int out_size) {
    const float* x1    = (const float*)d_in[0];
    const float* x2    = (const float*)d_in[1];
    const int*   ei12  = (const int*)d_in[2];
    const int*   ei21  = (const int*)d_in[3];
    const int*   pidx  = (const int*)d_in[4];
    const float* Win1  = (const float*)d_in[5];
    const float* bin1  = (const float*)d_in[6];
    const float* Win2  = (const float*)d_in[7];
    const float* bin2  = (const float*)d_in[8];
    const float* Wk    = (const float*)d_in[9];
    const float* bk    = (const float*)d_in[10];
    const float* Wq    = (const float*)d_in[11];
    const float* bq    = (const float*)d_in[12];
    const float* Wv    = (const float*)d_in[13];
    const float* bv    = (const float*)d_in[14];
    const float* Wa    = (const float*)d_in[15];
    const float* ba    = (const float*)d_in[16];
    const float* skip  = (const float*)d_in[17];
    const float* arel  = (const float*)d_in[18];
    const float* mrel  = (const float*)d_in[19];
    const float* prior = (const float*)d_in[20];
    float* out = (float*)d_out;

    const int E = in_sizes[2] / 2;
    const int P = in_sizes[4] / 2;

    float *h1, *h2, *q1, *kt1, *vt1, *q2, *kt2, *vt2, *agg1, *agg2, *s1, *s2;
    float *Em, *Ed, *Wkp, *bkp, *Wvp, *bvp;
    cudaGetSymbolAddress((void**)&h1,  g_h1);
    cudaGetSymbolAddress((void**)&h2,  g_h2);
    cudaGetSymbolAddress((void**)&q1,  g_q1);
    cudaGetSymbolAddress((void**)&kt1, g_kt1);
    cudaGetSymbolAddress((void**)&vt1, g_vt1);
    cudaGetSymbolAddress((void**)&q2,  g_q2);
    cudaGetSymbolAddress((void**)&kt2, g_kt2);
    cudaGetSymbolAddress((void**)&vt2, g_vt2);
    cudaGetSymbolAddress((void**)&agg1, g_agg1);
    cudaGetSymbolAddress((void**)&agg2, g_agg2);
    cudaGetSymbolAddress((void**)&s1,  g_s1);
    cudaGetSymbolAddress((void**)&s2,  g_s2);
    cudaGetSymbolAddress((void**)&Em,  g_Em);
    cudaGetSymbolAddress((void**)&Ed,  g_Ed);
    cudaGetSymbolAddress((void**)&Wkp, g_Wkp);
    cudaGetSymbolAddress((void**)&bkp, g_bkp);
    cudaGetSymbolAddress((void**)&Wvp, g_Wvp);
    cudaGetSymbolAddress((void**)&bvp, g_bvp);

    const int WW = CHID * CHID;
    dim3 gemmGrid1((CN1 + 63) / 64);
    dim3 gemmGrid2((CN2 + 63) / 64);

    prep_weights<<<dim3(4, 2), 256>>>(Wk, bk, Wv, bv, arel, mrel);

    // input projections + ReLU
    gemm128<<<gemmGrid1, 128>>>(x1, CF_IN, Win1, bin1, h1, CHID, CN1, CF_IN, 1,
                                nullptr, nullptr, 0, nullptr);
    gemm128<<<gemmGrid2, 128>>>(x2, CF_IN, Win2, bin2, h2, CHID, CN2, CF_IN, 1,
                                nullptr, nullptr, 0, nullptr);

    for (int l = 0; l < CNL; l++) {
        const float* A1 = (l == 0) ? h1 : (Em + (l - 1) * CHID);
        const float* A2 = (l == 0) ? h2 : (Ed + (l - 1) * CHID);
        int lda1 = (l == 0) ? CHID : CNL * CHID;
        int lda2 = (l == 0) ? CHID : CNL * CHID;
        int c0 = l * 2 + 0, c1 = l * 2 + 1;

        // projections: q (plain), kt (arel-folded), vt (mrel-folded)
        gemm128<<<gemmGrid1, 128>>>(A1, lda1, Wq + (size_t)c0 * WW, bq + c0 * CHID,
                                    q1, CHID, CN1, CHID, 0, nullptr, nullptr, 0, nullptr);
        gemm128<<<gemmGrid1, 128>>>(A1, lda1, Wkp + (size_t)c0 * WW, bkp + c0 * CHID,
                                    kt1, CHID, CN1, CHID, 0, nullptr, nullptr, 0, nullptr);
        gemm128<<<gemmGrid1, 128>>>(A1, lda1, Wvp + (size_t)c0 * WW, bvp + c0 * CHID,
                                    vt1, CHID, CN1, CHID, 0, nullptr, nullptr, 0, nullptr);
        gemm128<<<gemmGrid2, 128>>>(A2, lda2, Wq + (size_t)c1 * WW, bq + c1 * CHID,
                                    q2, CHID, CN2, CHID, 0, nullptr, nullptr, 0, nullptr);
        gemm128<<<gemmGrid2, 128>>>(A2, lda2, Wkp + (size_t)c1 * WW, bkp + c1 * CHID,
                                    kt2, CHID, CN2, CHID, 0, nullptr, nullptr, 0, nullptr);
        gemm128<<<gemmGrid2, 128>>>(A2, lda2, Wvp + (size_t)c1 * WW, bvp + c1 * CHID,
                                    vt2, CHID, CN2, CHID, 0, nullptr, nullptr, 0, nullptr);

        zero_bufs<<<(CN1 * CHID + 255) / 256, 256>>>();

        // edge type 0: n1 -> n2 (dst in N2); edge type 1: n2 -> n1 (dst in N1)
        edge_attend<<<(E * 32 + 255) / 256, 256>>>(ei12, E, q2, kt1, vt1,
                                                   prior + c0 * CNH, agg2, s2);
        edge_attend<<<(E * 32 + 255) / 256, 256>>>(ei21, E, q1, kt2, vt2,
                                                   prior + c1 * CNH, agg1, s1);

        // output GEMMs with fused softmax-normalize + GELU + gated skip
        const float* hold1 = (l == 0) ? h1 : Em;
        const float* hold2 = (l == 0) ? h2 : Ed;
        int ldh = (l == 0) ? CHID : CNL * CHID;
        gemm128<<<gemmGrid1, 128>>>(agg1, CHID, Wa + (size_t)c0 * WW, ba + c0 * CHID,
                                    Em + l * CHID, CNL * CHID, CN1, CHID, 2,
                                    s1, hold1, ldh, skip + c0);
        gemm128<<<gemmGrid2, 128>>>(agg2, CHID, Wa + (size_t)c1 * WW, ba + c1 * CHID,
                                    Ed + l * CHID, CNL * CHID, CN2, CHID, 2,
                                    s2, hold2, ldh, skip + c1);
    }

    pred_kernel<<<(P * 32 + 255) / 256, 256>>>(pidx, P, out);
}

// round 3
// speedup vs baseline: 1.1075x; 1.1075x over previous
#include <cuda_runtime.h>
#include <cuda_fp16.h>
#include <math.h>

#define CN1 10000
#define CN2 10000
#define CF_IN 256
#define CHID 128
#define CNH 8
#define CDH 16
#define CNL 2
#define QKVW 384   // packed q|kt|vt width

// ---------------- scratch (static device globals; no allocation) ----------------
__device__ float  g_h1[CN1 * CHID];
__device__ float  g_h2[CN2 * CHID];
__device__ __half g_qkv1[CN1 * QKVW];
__device__ __half g_qkv2[CN2 * QKVW];
__device__ float  g_agg1[CN1 * CHID], g_agg2[CN2 * CHID];
__device__ float  g_s1[CN1 * CNH], g_s2[CN2 * CNH];
__device__ float  g_Em[CN1 * CHID * CNL], g_Ed[CN2 * CHID * CNL];
__device__ float  g_Wcat[CNL * 2 * CHID * QKVW];  // per (l,t): [K=128][384] q|ktfold|vtfold
__device__ float  g_bcat[CNL * 2 * QKVW];

// ---------------- helpers ----------------
__device__ __forceinline__ float gelu_f(float x) {
    float x3 = x * x * x;
    return 0.5f * x * (1.0f + tanhf(0.7978845608028654f * (x + 0.044715f * x3)));
}

__device__ __forceinline__ void red_add4(float* p, float a, float b, float c, float d) {
    asm volatile("red.global.add.v4.f32 [%0], {%1,%2,%3,%4};"
                 :: "l"(p), "f"(a), "f"(b), "f"(c), "f"(d) : "memory");
}

// ---------------- build packed weights: [128][384] = Wq | Wk@arel | Wv@mrel ----------------
__global__ void prep_cat(const float* __restrict__ Wq, const float* __restrict__ bq,
                         const float* __restrict__ Wk, const float* __restrict__ bk,
                         const float* __restrict__ Wv, const float* __restrict__ bv,
                         const float* __restrict__ arel, const float* __restrict__ mrel) {
    int combo = blockIdx.x;  // l*2+t
    const int WW = CHID * CHID;
    float* Wcat = g_Wcat + (size_t)combo * CHID * QKVW;
    float* bcat = g_bcat + combo * QKVW;
    int tid = threadIdx.x;
    for (int i = tid; i < CHID * QKVW; i += blockDim.x) {
        int c = i / QKVW, col = i % QKVW;
        float val;
        if (col < 128) {
            val = Wq[(size_t)combo * WW + c * CHID + col];
        } else if (col < 256) {
            int cc = col - 128, h = cc >> 4, e = cc & 15;
            const float* rel = arel + (size_t)combo * CNH * CDH * CDH + h * CDH * CDH;
            float acc = 0.f;
#pragma unroll
            for (int d = 0; d < CDH; d++)
                acc += Wk[(size_t)combo * WW + c * CHID + h * CDH + d] * rel[d * CDH + e];
            val = acc;
        } else {
            int cc = col - 256, h = cc >> 4, e = cc & 15;
            const float* rel = mrel + (size_t)combo * CNH * CDH * CDH + h * CDH * CDH;
            float acc = 0.f;
#pragma unroll
            for (int d = 0; d < CDH; d++)
                acc += Wv[(size_t)combo * WW + c * CHID + h * CDH + d] * rel[d * CDH + e];
            val = acc;
        }
        Wcat[i] = val;
    }
    if (tid < QKVW) {
        int col = tid;
        float val;
        if (col < 128) {
            val = bq[combo * CHID + col];
        } else if (col < 256) {
            int cc = col - 128, h = cc >> 4, e = cc & 15;
            const float* rel = arel + (size_t)combo * CNH * CDH * CDH + h * CDH * CDH;
            float acc = 0.f;
#pragma unroll
            for (int d = 0; d < CDH; d++) acc += bk[combo * CHID + h * CDH + d] * rel[d * CDH + e];
            val = acc;
        } else {
            int cc = col - 256, h = cc >> 4, e = cc & 15;
            const float* rel = mrel + (size_t)combo * CNH * CDH * CDH + h * CDH * CDH;
            float acc = 0.f;
#pragma unroll
            for (int d = 0; d < CDH; d++) acc += bv[combo * CHID + h * CDH + d] * rel[d * CDH + e];
            val = acc;
        }
        bcat[col] = val;
    }
}

// ---------------- zero accumulators ----------------
__global__ void zero_bufs() {
    int tid = blockIdx.x * blockDim.x + threadIdx.x;
    if (tid < CN1 * CHID) { g_agg1[tid] = 0.f; g_agg2[tid] = 0.f; }
    if (tid < CN1 * CNH)  { g_s1[tid] = 0.f;  g_s2[tid] = 0.f; }
}

// ---------------- [M,K]@[K,N] GEMM, BM=128 BN=128 tiles, 256 threads, 8x8/thread ----------------
// mode 1: Cf = relu(A@B + bias)                                     (f32 out)
// mode 2: A' = gelu(A / (sdiv + 1e-16)); Cf = sg*(A'@B+bias)+(1-sg)*hold
// mode 3: Ch = half(A@B + bias)                                     (half out)
__global__ void __launch_bounds__(256)
gemm_k(const float* __restrict__ A, int lda,
       const float* __restrict__ B, int ldb, const float* __restrict__ bias,
       float* __restrict__ Cf, int ldcf,
       __half* __restrict__ Ch, int ldch,
       int M, int K, int mode,
       const float* __restrict__ sdiv,
       const float* __restrict__ hold, int ldh,
       const float* __restrict__ skipp) {
    __shared__ float As[32][132];   // [k][m]
    __shared__ float Bs[32][132];   // [k][n]

    int tid = threadIdx.x;
    int tx = tid & 15;              // 16 col groups of 8
    int ty = tid >> 4;              // 16 row groups of 8
    int m0 = blockIdx.x * 128;
    int n0 = blockIdx.y * 128;

    float acc[8][8];
#pragma unroll
    for (int i = 0; i < 8; i++)
#pragma unroll
        for (int j = 0; j < 8; j++) acc[i][j] = 0.f;

    for (int k0 = 0; k0 < K; k0 += 32) {
        // A tile: 128x32 -> As[k][m]; 16 floats (4x float4) per thread
#pragma unroll
        for (int i = 0; i < 4; i++) {
            int lin = tid + i * 256;
            int row = lin >> 3;
            int kc  = (lin & 7) << 2;
            float4 v = make_float4(0.f, 0.f, 0.f, 0.f);
            int m = m0 + row;
            if (m < M) {
                v = *(const float4*)(A + (size_t)m * lda + k0 + kc);
                if (mode == 2) {
                    float inv = 1.0f / (sdiv[m * CNH + ((k0 + kc) >> 4)] + 1e-16f);
                    v.x = gelu_f(v.x * inv); v.y = gelu_f(v.y * inv);
                    v.z = gelu_f(v.z * inv); v.w = gelu_f(v.w * inv);
                }
            }
            As[kc + 0][row] = v.x; As[kc + 1][row] = v.y;
            As[kc + 2][row] = v.z; As[kc + 3][row] = v.w;
        }
        // B tile: 32x128; 16 floats per thread
#pragma unroll
        for (int i = 0; i < 4; i++) {
            int lin = tid + i * 256;
            int kr = lin >> 5;
            int nc = (lin & 31) << 2;
            *(float4*)&Bs[kr][nc] = *(const float4*)(B + (size_t)(k0 + kr) * ldb + n0 + nc);
        }
        __syncthreads();

#pragma unroll 8
        for (int kk = 0; kk < 32; kk++) {
            float a[8], b[8];
            float4 t0 = *(const float4*)&As[kk][ty * 8];
            float4 t1 = *(const float4*)&As[kk][ty * 8 + 4];
            a[0]=t0.x; a[1]=t0.y; a[2]=t0.z; a[3]=t0.w;
            a[4]=t1.x; a[5]=t1.y; a[6]=t1.z; a[7]=t1.w;
            float4 u0 = *(const float4*)&Bs[kk][tx * 8];
            float4 u1 = *(const float4*)&Bs[kk][tx * 8 + 4];
            b[0]=u0.x; b[1]=u0.y; b[2]=u0.z; b[3]=u0.w;
            b[4]=u1.x; b[5]=u1.y; b[6]=u1.z; b[7]=u1.w;
#pragma unroll
            for (int i = 0; i < 8; i++)
#pragma unroll
                for (int j = 0; j < 8; j++)
                    acc[i][j] += a[i] * b[j];
        }
        __syncthreads();
    }

    float sg = 1.f, sg1 = 0.f;
    if (mode == 2) {
        sg = 1.0f / (1.0f + __expf(-*skipp));
        sg1 = 1.0f - sg;
    }
#pragma unroll
    for (int i = 0; i < 8; i++) {
        int m = m0 + ty * 8 + i;
        if (m >= M) continue;
#pragma unroll
        for (int jj = 0; jj < 2; jj++) {
            int n = tx * 8 + jj * 4;
            float4 r;
            r.x = acc[i][jj * 4 + 0] + bias[n0 + n + 0];
            r.y = acc[i][jj * 4 + 1] + bias[n0 + n + 1];
            r.z = acc[i][jj * 4 + 2] + bias[n0 + n + 2];
            r.w = acc[i][jj * 4 + 3] + bias[n0 + n + 3];
            if (mode == 1) {
                r.x = fmaxf(r.x, 0.f); r.y = fmaxf(r.y, 0.f);
                r.z = fmaxf(r.z, 0.f); r.w = fmaxf(r.w, 0.f);
                *(float4*)(Cf + (size_t)m * ldcf + n0 + n) = r;
            } else if (mode == 2) {
                const float* hp = hold + (size_t)m * ldh + n0 + n;
                r.x = sg * r.x + sg1 * hp[0];
                r.y = sg * r.y + sg1 * hp[1];
                r.z = sg * r.z + sg1 * hp[2];
                r.w = sg * r.w + sg1 * hp[3];
                *(float4*)(Cf + (size_t)m * ldcf + n0 + n) = r;
            } else { // mode 3: half output
                __half2 p0 = __floats2half2_rn(r.x, r.y);
                __half2 p1 = __floats2half2_rn(r.z, r.w);
                uint2 pk;
                pk.x = *(unsigned*)&p0;
                pk.y = *(unsigned*)&p1;
                *(uint2*)(Ch + (size_t)m * ldch + n0 + n) = pk;
            }
        }
    }
}

// ---------------- edge attention (one warp per edge, fp16 gathers) ----------------
__global__ void __launch_bounds__(256)
edge_attend(const int* __restrict__ ei, int E,
            const __half* __restrict__ qkvd,   // q at dst rows
            const __half* __restrict__ qkvs,   // kt/vt at src rows
            const float* __restrict__ prior,
            float* __restrict__ agg,
            float* __restrict__ s) {
    int warp = (blockIdx.x * blockDim.x + threadIdx.x) >> 5;
    int lane = threadIdx.x & 31;
    if (warp >= E) return;
    int src = ei[warp];
    int dst = ei[E + warp];

    const uint2* qp = (const uint2*)(qkvd + (size_t)dst * QKVW) + lane;        // q[0:128]
    const uint2* kp = (const uint2*)(qkvs + (size_t)src * QKVW + 128) + lane;  // kt
    const uint2* vp = (const uint2*)(qkvs + (size_t)src * QKVW + 256) + lane;  // vt

    uint2 qw = __ldg(qp);
    uint2 kw = __ldg(kp);
    uint2 vw = __ldg(vp);

    float2 qa = __half22float2(*(__half2*)&qw.x), qb = __half22float2(*(__half2*)&qw.y);
    float2 ka = __half22float2(*(__half2*)&kw.x), kb = __half22float2(*(__half2*)&kw.y);
    float d = qa.x * ka.x + qa.y * ka.y + qb.x * kb.x + qb.y * kb.y;
    d += __shfl_xor_sync(0xffffffffu, d, 1);
    d += __shfl_xor_sync(0xffffffffu, d, 2);
    int h = lane >> 2;
    float e = __expf(d * __ldg(prior + h) * 0.25f);

    if ((lane & 3) == 0)
        atomicAdd(s + (size_t)dst * CNH + h, e);

    float2 va = __half22float2(*(__half2*)&vw.x), vb = __half22float2(*(__half2*)&vw.y);
    red_add4(agg + (size_t)dst * CHID + lane * 4, e * va.x, e * va.y, e * vb.x, e * vb.y);
}

// ---------------- final pair scores (one warp per pair) ----------------
__global__ void __launch_bounds__(256)
pred_kernel(const int* __restrict__ pidx, int P, float* __restrict__ out) {
    int warp = (blockIdx.x * blockDim.x + threadIdx.x) >> 5;
    int lane = threadIdx.x & 31;
    if (warp >= P) return;
    int i = pidx[warp];
    int j = pidx[P + warp];
    const float4* em = (const float4*)(g_Em + (size_t)i * (CHID * CNL));
    const float4* ed = (const float4*)(g_Ed + (size_t)j * (CHID * CNL));
    float4 a0 = em[lane],      b0 = ed[lane];
    float4 a1 = em[32 + lane], b1 = ed[32 + lane];
    float d = a0.x * b0.x + a0.y * b0.y + a0.z * b0.z + a0.w * b0.w
            + a1.x * b1.x + a1.y * b1.y + a1.z * b1.z + a1.w * b1.w;
#pragma unroll
    for (int o = 16; o > 0; o >>= 1) d += __shfl_xor_sync(0xffffffffu, d, o);
    if (lane == 0) out[warp] = d;
}

// ---------------- host driver ----------------
extern "C" void kernel_launch(void* const* d_in, const int* in_sizes, int n_in,
                              void* d_out, int out_size) {
    const float* x1    = (const float*)d_in[0];
    const float* x2    = (const float*)d_in[1];
    const int*   ei12  = (const int*)d_in[2];
    const int*   ei21  = (const int*)d_in[3];
    const int*   pidx  = (const int*)d_in[4];
    const float* Win1  = (const float*)d_in[5];
    const float* bin1  = (const float*)d_in[6];
    const float* Win2  = (const float*)d_in[7];
    const float* bin2  = (const float*)d_in[8];
    const float* Wk    = (const float*)d_in[9];
    const float* bk    = (const float*)d_in[10];
    const float* Wq    = (const float*)d_in[11];
    const float* bq    = (const float*)d_in[12];
    const float* Wv    = (const float*)d_in[13];
    const float* bv    = (const float*)d_in[14];
    const float* Wa    = (const float*)d_in[15];
    const float* ba    = (const float*)d_in[16];
    const float* skip  = (const float*)d_in[17];
    const float* arel  = (const float*)d_in[18];
    const float* mrel  = (const float*)d_in[19];
    const float* prior = (const float*)d_in[20];
    float* out = (float*)d_out;

    const int E = in_sizes[2] / 2;
    const int P = in_sizes[4] / 2;

    float *h1, *h2, *agg1, *agg2, *s1, *s2, *Em, *Ed, *Wcat, *bcat;
    __half *qkv1, *qkv2;
    cudaGetSymbolAddress((void**)&h1,   g_h1);
    cudaGetSymbolAddress((void**)&h2,   g_h2);
    cudaGetSymbolAddress((void**)&qkv1, g_qkv1);
    cudaGetSymbolAddress((void**)&qkv2, g_qkv2);
    cudaGetSymbolAddress((void**)&agg1, g_agg1);
    cudaGetSymbolAddress((void**)&agg2, g_agg2);
    cudaGetSymbolAddress((void**)&s1,   g_s1);
    cudaGetSymbolAddress((void**)&s2,   g_s2);
    cudaGetSymbolAddress((void**)&Em,   g_Em);
    cudaGetSymbolAddress((void**)&Ed,   g_Ed);
    cudaGetSymbolAddress((void**)&Wcat, g_Wcat);
    cudaGetSymbolAddress((void**)&bcat, g_bcat);

    const int WW = CHID * CHID;
    dim3 g1((CN1 + 127) / 128);        // 79
    dim3 g1q((CN1 + 127) / 128, 3);    // qkv: N=384
    dim3 g2((CN2 + 127) / 128);
    dim3 g2q((CN2 + 127) / 128, 3);

    prep_cat<<<4, 256>>>(Wq, bq, Wk, bk, Wv, bv, arel, mrel);

    // input projections + ReLU (f32 out)
    gemm_k<<<g1, 256>>>(x1, CF_IN, Win1, CHID, bin1, h1, CHID, nullptr, 0,
                        CN1, CF_IN, 1, nullptr, nullptr, 0, nullptr);
    gemm_k<<<g2, 256>>>(x2, CF_IN, Win2, CHID, bin2, h2, CHID, nullptr, 0,
                        CN2, CF_IN, 1, nullptr, nullptr, 0, nullptr);

    for (int l = 0; l < CNL; l++) {
        const float* A1 = (l == 0) ? h1 : Em;   // current h1 lives in Em cols [0,128)
        const float* A2 = (l == 0) ? h2 : Ed;
        int lda = (l == 0) ? CHID : CNL * CHID;
        int c0 = l * 2 + 0, c1 = l * 2 + 1;

        // fused q|kt|vt projections -> packed half qkv buffers
        gemm_k<<<g1q, 256>>>(A1, lda, Wcat + (size_t)c0 * CHID * QKVW, QKVW,
                             bcat + c0 * QKVW, nullptr, 0, qkv1, QKVW,
                             CN1, CHID, 3, nullptr, nullptr, 0, nullptr);
        gemm_k<<<g2q, 256>>>(A2, lda, Wcat + (size_t)c1 * CHID * QKVW, QKVW,
                             bcat + c1 * QKVW, nullptr, 0, qkv2, QKVW,
                             CN2, CHID, 3, nullptr, nullptr, 0, nullptr);

        zero_bufs<<<(CN1 * CHID + 255) / 256, 256>>>();

        // edge type 0: n1 -> n2 (dst in N2); edge type 1: n2 -> n1 (dst in N1)
        edge_attend<<<(E * 32 + 255) / 256, 256>>>(ei12, E, qkv2, qkv1,
                                                   prior + c0 * CNH, agg2, s2);
        edge_attend<<<(E * 32 + 255) / 256, 256>>>(ei21, E, qkv1, qkv2,
                                                   prior + c1 * CNH, agg1, s1);

        // output GEMMs: fused softmax-normalize + GELU + gated skip
        const float* hold1 = (l == 0) ? h1 : Em;
        const float* hold2 = (l == 0) ? h2 : Ed;
        int ldh = (l == 0) ? CHID : CNL * CHID;
        gemm_k<<<g1, 256>>>(agg1, CHID, Wa + (size_t)c0 * WW, CHID, ba + c0 * CHID,
                            Em + l * CHID, CNL * CHID, nullptr, 0,
                            CN1, CHID, 2, s1, hold1, ldh, skip + c0);
        gemm_k<<<g2, 256>>>(agg2, CHID, Wa + (size_t)c1 * WW, CHID, ba + c1 * CHID,
                            Ed + l * CHID, CNL * CHID, nullptr, 0,
                            CN2, CHID, 2, s2, hold2, ldh, skip + c1);
    }

    pred_kernel<<<(P * 32 + 255) / 256, 256>>>(pidx, P, out);
}

// round 5
// speedup vs baseline: 1.1586x; 1.0461x over previous
#include <cuda_runtime.h>
#include <cuda_fp16.h>
#include <math.h>

#define CN1 10000
#define CN2 10000
#define CF_IN 256
#define CHID 128
#define CNH 8
#define CDH 16
#define CNL 2
#define QKVW 384
#define EMAX 480000

// ---------------- scratch (static device globals) ----------------
__device__ float  g_h1[CN1 * CHID];
__device__ float  g_h2[CN2 * CHID];
__device__ __half g_qkv1[CN1 * QKVW];
__device__ __half g_qkv2[CN2 * QKVW];
__device__ float  g_agg1[CN1 * CHID], g_agg2[CN2 * CHID];
__device__ float  g_Em[CN1 * CHID * CNL], g_Ed[CN2 * CHID * CNL];
__device__ float  g_Wcat[CNL * 2 * CHID * QKVW];
__device__ float  g_bcat[CNL * 2 * QKVW];
// CSR scratch
__device__ int g_cnt12[CN2], g_cnt21[CN1];
__device__ int g_rp12[CN2 + 1], g_rp21[CN1 + 1];
__device__ int g_cur12[CN2], g_cur21[CN1];
__device__ int g_src12[EMAX], g_src21[EMAX];

// ---------------- helpers ----------------
__device__ __forceinline__ float gelu_f(float x) {
    float x3 = x * x * x;
    return 0.5f * x * (1.0f + tanhf(0.7978845608028654f * (x + 0.044715f * x3)));
}

// ---------------- build packed weights: [128][384] = Wq | Wk@arel | Wv@mrel ----------------
__global__ void prep_cat(const float* __restrict__ Wq, const float* __restrict__ bq,
                         const float* __restrict__ Wk, const float* __restrict__ bk,
                         const float* __restrict__ Wv, const float* __restrict__ bv,
                         const float* __restrict__ arel, const float* __restrict__ mrel) {
    int combo = blockIdx.x;
    const int WW = CHID * CHID;
    float* Wcat = g_Wcat + (size_t)combo * CHID * QKVW;
    float* bcat = g_bcat + combo * QKVW;
    int tid = threadIdx.x;
    for (int i = tid; i < CHID * QKVW; i += blockDim.x) {
        int c = i / QKVW, col = i % QKVW;
        float val;
        if (col < 128) {
            val = Wq[(size_t)combo * WW + c * CHID + col];
        } else if (col < 256) {
            int cc = col - 128, h = cc >> 4, e = cc & 15;
            const float* rel = arel + (size_t)combo * CNH * CDH * CDH + h * CDH * CDH;
            float acc = 0.f;
#pragma unroll
            for (int d = 0; d < CDH; d++)
                acc += Wk[(size_t)combo * WW + c * CHID + h * CDH + d] * rel[d * CDH + e];
            val = acc;
        } else {
            int cc = col - 256, h = cc >> 4, e = cc & 15;
            const float* rel = mrel + (size_t)combo * CNH * CDH * CDH + h * CDH * CDH;
            float acc = 0.f;
#pragma unroll
            for (int d = 0; d < CDH; d++)
                acc += Wv[(size_t)combo * WW + c * CHID + h * CDH + d] * rel[d * CDH + e];
            val = acc;
        }
        Wcat[i] = val;
    }
    if (tid < QKVW) {
        int col = tid;
        float val;
        if (col < 128) {
            val = bq[combo * CHID + col];
        } else if (col < 256) {
            int cc = col - 128, h = cc >> 4, e = cc & 15;
            const float* rel = arel + (size_t)combo * CNH * CDH * CDH + h * CDH * CDH;
            float acc = 0.f;
#pragma unroll
            for (int d = 0; d < CDH; d++) acc += bk[combo * CHID + h * CDH + d] * rel[d * CDH + e];
            val = acc;
        } else {
            int cc = col - 256, h = cc >> 4, e = cc & 15;
            const float* rel = mrel + (size_t)combo * CNH * CDH * CDH + h * CDH * CDH;
            float acc = 0.f;
#pragma unroll
            for (int d = 0; d < CDH; d++) acc += bv[combo * CHID + h * CDH + d] * rel[d * CDH + e];
            val = acc;
        }
        bcat[col] = val;
    }
}

// ---------------- CSR build ----------------
__global__ void csr_zero() {
    int i = blockIdx.x * blockDim.x + threadIdx.x;
    if (i < CN2) g_cnt12[i] = 0;
    if (i < CN1) g_cnt21[i] = 0;
}

__global__ void csr_hist(const int* __restrict__ ei12, const int* __restrict__ ei21, int E) {
    int i = blockIdx.x * blockDim.x + threadIdx.x;
    if (i < E) atomicAdd(&g_cnt12[ei12[E + i]], 1);
    else if (i < 2 * E) { int j = i - E; atomicAdd(&g_cnt21[ei21[E + j]], 1); }
}

__global__ void __launch_bounds__(1024) csr_scan(int n) {
    int dir = blockIdx.x;
    const int* cnt = dir ? g_cnt21 : g_cnt12;
    int* rp  = dir ? g_rp21 : g_rp12;
    int* cur = dir ? g_cur21 : g_cur12;
    __shared__ int sums[1024];
    int t = threadIdx.x;
    int chunk = (n + 1023) / 1024;
    int s0 = t * chunk;
    int local = 0;
    for (int i = 0; i < chunk; i++) if (s0 + i < n) local += cnt[s0 + i];
    sums[t] = local;
    __syncthreads();
    for (int off = 1; off < 1024; off <<= 1) {
        int v = (t >= off) ? sums[t - off] : 0;
        __syncthreads();
        sums[t] += v;
        __syncthreads();
    }
    int run = (t == 0) ? 0 : sums[t - 1];
    for (int i = 0; i < chunk; i++) if (s0 + i < n) {
        rp[s0 + i] = run; cur[s0 + i] = run; run += cnt[s0 + i];
    }
    if (t == 1023) rp[n] = run;
}

__global__ void csr_scatter(const int* __restrict__ ei12, const int* __restrict__ ei21, int E) {
    int i = blockIdx.x * blockDim.x + threadIdx.x;
    if (i < E) {
        int dst = ei12[E + i];
        int pos = atomicAdd(&g_cur12[dst], 1);
        g_src12[pos] = ei12[i];
    } else if (i < 2 * E) {
        int j = i - E;
        int dst = ei21[E + j];
        int pos = atomicAdd(&g_cur21[dst], 1);
        g_src21[pos] = ei21[j];
    }
}

// ---------------- GEMM: two jobs per launch (blockIdx.z) ----------------
struct GJob {
    const float* A; int lda;
    const float* B; int ldb;
    const float* bias;
    float* Cf; int ldcf;
    __half* Ch; int ldch;
    int M, K;
    const float* hold; int ldh;
    const float* skipp;
};

// mode 1: Cf = relu(A@B+bias); mode 2: Cf = sg*(gelu(A)@B+bias)+(1-sg)*hold; mode 3: Ch = half(A@B+bias)
__global__ void __launch_bounds__(256)
gemm_k(GJob j0, GJob j1, int mode) {
    GJob jb = blockIdx.z ? j1 : j0;
    __shared__ float As[32][132];
    __shared__ float Bs[32][132];

    int tid = threadIdx.x;
    int tx = tid & 15;
    int ty = tid >> 4;
    int m0 = blockIdx.x * 128;
    int n0 = blockIdx.y * 128;

    float acc[8][8];
#pragma unroll
    for (int i = 0; i < 8; i++)
#pragma unroll
        for (int j = 0; j < 8; j++) acc[i][j] = 0.f;

    for (int k0 = 0; k0 < jb.K; k0 += 32) {
#pragma unroll
        for (int i = 0; i < 4; i++) {
            int lin = tid + i * 256;
            int row = lin >> 3;
            int kc  = (lin & 7) << 2;
            float4 v = make_float4(0.f, 0.f, 0.f, 0.f);
            int m = m0 + row;
            if (m < jb.M) {
                v = *(const float4*)(jb.A + (size_t)m * jb.lda + k0 + kc);
                if (mode == 2) {
                    v.x = gelu_f(v.x); v.y = gelu_f(v.y);
                    v.z = gelu_f(v.z); v.w = gelu_f(v.w);
                }
            }
            As[kc + 0][row] = v.x; As[kc + 1][row] = v.y;
            As[kc + 2][row] = v.z; As[kc + 3][row] = v.w;
        }
#pragma unroll
        for (int i = 0; i < 4; i++) {
            int lin = tid + i * 256;
            int kr = lin >> 5;
            int nc = (lin & 31) << 2;
            *(float4*)&Bs[kr][nc] = *(const float4*)(jb.B + (size_t)(k0 + kr) * jb.ldb + n0 + nc);
        }
        __syncthreads();

#pragma unroll 8
        for (int kk = 0; kk < 32; kk++) {
            float a[8], b[8];
            float4 t0 = *(const float4*)&As[kk][ty * 8];
            float4 t1 = *(const float4*)&As[kk][ty * 8 + 4];
            a[0]=t0.x; a[1]=t0.y; a[2]=t0.z; a[3]=t0.w;
            a[4]=t1.x; a[5]=t1.y; a[6]=t1.z; a[7]=t1.w;
            float4 u0 = *(const float4*)&Bs[kk][tx * 8];
            float4 u1 = *(const float4*)&Bs[kk][tx * 8 + 4];
            b[0]=u0.x; b[1]=u0.y; b[2]=u0.z; b[3]=u0.w;
            b[4]=u1.x; b[5]=u1.y; b[6]=u1.z; b[7]=u1.w;
#pragma unroll
            for (int i = 0; i < 8; i++)
#pragma unroll
                for (int j = 0; j < 8; j++)
                    acc[i][j] += a[i] * b[j];
        }
        __syncthreads();
    }

    float sg = 1.f, sg1 = 0.f;
    if (mode == 2) {
        sg = 1.0f / (1.0f + __expf(-*jb.skipp));
        sg1 = 1.0f - sg;
    }
#pragma unroll
    for (int i = 0; i < 8; i++) {
        int m = m0 + ty * 8 + i;
        if (m >= jb.M) continue;
#pragma unroll
        for (int jj = 0; jj < 2; jj++) {
            int n = tx * 8 + jj * 4;
            float4 r;
            r.x = acc[i][jj * 4 + 0] + jb.bias[n0 + n + 0];
            r.y = acc[i][jj * 4 + 1] + jb.bias[n0 + n + 1];
            r.z = acc[i][jj * 4 + 2] + jb.bias[n0 + n + 2];
            r.w = acc[i][jj * 4 + 3] + jb.bias[n0 + n + 3];
            if (mode == 1) {
                r.x = fmaxf(r.x, 0.f); r.y = fmaxf(r.y, 0.f);
                r.z = fmaxf(r.z, 0.f); r.w = fmaxf(r.w, 0.f);
                *(float4*)(jb.Cf + (size_t)m * jb.ldcf + n0 + n) = r;
            } else if (mode == 2) {
                const float* hp = jb.hold + (size_t)m * jb.ldh + n0 + n;
                r.x = sg * r.x + sg1 * hp[0];
                r.y = sg * r.y + sg1 * hp[1];
                r.z = sg * r.z + sg1 * hp[2];
                r.w = sg * r.w + sg1 * hp[3];
                *(float4*)(jb.Cf + (size_t)m * jb.ldcf + n0 + n) = r;
            } else {
                __half2 p0 = __floats2half2_rn(r.x, r.y);
                __half2 p1 = __floats2half2_rn(r.z, r.w);
                uint2 pk;
                pk.x = *(unsigned*)&p0;
                pk.y = *(unsigned*)&p1;
                *(uint2*)(jb.Ch + (size_t)m * jb.ldch + n0 + n) = pk;
            }
        }
    }
}

// ---------------- CSR attention: one warp per dst node, both directions in one launch ----------------
struct AJob {
    const int* rp; const int* col;
    const __half* qkv_dst; const __half* qkv_src;
    const float* prior;
    float* agg;
    int n;
};

__global__ void __launch_bounds__(256)
attend_csr(AJob a, AJob b) {
    int gw = (blockIdx.x * blockDim.x + threadIdx.x) >> 5;
    int lane = threadIdx.x & 31;
    int total = a.n + b.n;
    if (gw >= total) return;
    AJob jb = (gw < a.n) ? a : b;
    int dst = (gw < a.n) ? gw : gw - a.n;

    int start = __ldg(jb.rp + dst);
    int end   = __ldg(jb.rp + dst + 1);

    // q for this dst: 4 halfs per lane
    uint2 qw = __ldg((const uint2*)(jb.qkv_dst + (size_t)dst * QKVW) + lane);
    float2 qa = __half22float2(*(__half2*)&qw.x), qb2 = __half22float2(*(__half2*)&qw.y);
    int h = lane >> 2;
    float scale = __ldg(jb.prior + h) * 0.25f;

    float acc0 = 0.f, acc1 = 0.f, acc2 = 0.f, acc3 = 0.f, ssum = 0.f;

    for (int base = start; base < end; base += 32) {
        int myc = (base + lane < end) ? __ldg(jb.col + base + lane) : 0;
        int cnt = min(32, end - base);
        for (int jj = 0; jj < cnt; jj++) {
            int src = __shfl_sync(0xffffffffu, myc, jj);
            const __half* sp = jb.qkv_src + (size_t)src * QKVW;
            uint2 kw = __ldg((const uint2*)(sp + 128) + lane);
            uint2 vw = __ldg((const uint2*)(sp + 256) + lane);
            float2 ka = __half22float2(*(__half2*)&kw.x), kb = __half22float2(*(__half2*)&kw.y);
            float d = qa.x * ka.x + qa.y * ka.y + qb2.x * kb.x + qb2.y * kb.y;
            d += __shfl_xor_sync(0xffffffffu, d, 1);
            d += __shfl_xor_sync(0xffffffffu, d, 2);
            float e = __expf(d * scale);
            ssum += e;
            float2 va = __half22float2(*(__half2*)&vw.x), vb = __half22float2(*(__half2*)&vw.y);
            acc0 += e * va.x; acc1 += e * va.y; acc2 += e * vb.x; acc3 += e * vb.y;
        }
    }

    float inv = 1.0f / (ssum + 1e-16f);
    float4 r = make_float4(acc0 * inv, acc1 * inv, acc2 * inv, acc3 * inv);
    *(float4*)(jb.agg + (size_t)dst * CHID + lane * 4) = r;
}

// ---------------- final pair scores ----------------
__global__ void __launch_bounds__(256)
pred_kernel(const int* __restrict__ pidx, int P, float* __restrict__ out) {
    int warp = (blockIdx.x * blockDim.x + threadIdx.x) >> 5;
    int lane = threadIdx.x & 31;
    if (warp >= P) return;
    int i = pidx[warp];
    int j = pidx[P + warp];
    const float4* em = (const float4*)(g_Em + (size_t)i * (CHID * CNL));
    const float4* ed = (const float4*)(g_Ed + (size_t)j * (CHID * CNL));
    float4 a0 = em[lane],      b0 = ed[lane];
    float4 a1 = em[32 + lane], b1 = ed[32 + lane];
    float d = a0.x * b0.x + a0.y * b0.y + a0.z * b0.z + a0.w * b0.w
            + a1.x * b1.x + a1.y * b1.y + a1.z * b1.z + a1.w * b1.w;
#pragma unroll
    for (int o = 16; o > 0; o >>= 1) d += __shfl_xor_sync(0xffffffffu, d, o);
    if (lane == 0) out[warp] = d;
}

// ---------------- host driver ----------------
extern "C" void kernel_launch(void* const* d_in, const int* in_sizes, int n_in,
                              void* d_out, int out_size) {
    const float* x1    = (const float*)d_in[0];
    const float* x2    = (const float*)d_in[1];
    const int*   ei12  = (const int*)d_in[2];
    const int*   ei21  = (const int*)d_in[3];
    const int*   pidx  = (const int*)d_in[4];
    const float* Win1  = (const float*)d_in[5];
    const float* bin1  = (const float*)d_in[6];
    const float* Win2  = (const float*)d_in[7];
    const float* bin2  = (const float*)d_in[8];
    const float* Wk    = (const float*)d_in[9];
    const float* bk    = (const float*)d_in[10];
    const float* Wq    = (const float*)d_in[11];
    const float* bq    = (const float*)d_in[12];
    const float* Wv    = (const float*)d_in[13];
    const float* bv    = (const float*)d_in[14];
    const float* Wa    = (const float*)d_in[15];
    const float* ba    = (const float*)d_in[16];
    const float* skip  = (const float*)d_in[17];
    const float* arel  = (const float*)d_in[18];
    const float* mrel  = (const float*)d_in[19];
    const float* prior = (const float*)d_in[20];
    float* out = (float*)d_out;

    const int E = in_sizes[2] / 2;
    const int P = in_sizes[4] / 2;

    float *h1, *h2, *agg1, *agg2, *Em, *Ed, *Wcat, *bcat;
    __half *qkv1, *qkv2;
    int *rp12, *rp21, *src12, *src21;
    cudaGetSymbolAddress((void**)&h1,   g_h1);
    cudaGetSymbolAddress((void**)&h2,   g_h2);
    cudaGetSymbolAddress((void**)&qkv1, g_qkv1);
    cudaGetSymbolAddress((void**)&qkv2, g_qkv2);
    cudaGetSymbolAddress((void**)&agg1, g_agg1);
    cudaGetSymbolAddress((void**)&agg2, g_agg2);
    cudaGetSymbolAddress((void**)&Em,   g_Em);
    cudaGetSymbolAddress((void**)&Ed,   g_Ed);
    cudaGetSymbolAddress((void**)&Wcat, g_Wcat);
    cudaGetSymbolAddress((void**)&bcat, g_bcat);
    cudaGetSymbolAddress((void**)&rp12, g_rp12);
    cudaGetSymbolAddress((void**)&rp21, g_rp21);
    cudaGetSymbolAddress((void**)&src12, g_src12);
    cudaGetSymbolAddress((void**)&src21, g_src21);

    const int WW = CHID * CHID;

    prep_cat<<<4, 256>>>(Wq, bq, Wk, bk, Wv, bv, arel, mrel);

    // CSR build (once; reused by both layers)
    csr_zero<<<(CN1 + 255) / 256, 256>>>();
    csr_hist<<<(2 * E + 255) / 256, 256>>>(ei12, ei21, E);
    csr_scan<<<2, 1024>>>(CN1);
    csr_scatter<<<(2 * E + 255) / 256, 256>>>(ei12, ei21, E);

    // input projections + ReLU (both node types in one launch)
    {
        GJob j0 = { x1, CF_IN, Win1, CHID, bin1, h1, CHID, nullptr, 0, CN1, CF_IN, nullptr, 0, nullptr };
        GJob j1 = { x2, CF_IN, Win2, CHID, bin2, h2, CHID, nullptr, 0, CN2, CF_IN, nullptr, 0, nullptr };
        gemm_k<<<dim3((CN1 + 127) / 128, 1, 2), 256>>>(j0, j1, 1);
    }

    for (int l = 0; l < CNL; l++) {
        const float* A1 = (l == 0) ? h1 : Em;
        const float* A2 = (l == 0) ? h2 : Ed;
        int lda = (l == 0) ? CHID : CNL * CHID;
        int c0 = l * 2 + 0, c1 = l * 2 + 1;

        // fused q|kt|vt projections -> packed half qkv (both types, one launch)
        {
            GJob j0 = { A1, lda, Wcat + (size_t)c0 * CHID * QKVW, QKVW, bcat + c0 * QKVW,
                        nullptr, 0, qkv1, QKVW, CN1, CHID, nullptr, 0, nullptr };
            GJob j1 = { A2, lda, Wcat + (size_t)c1 * CHID * QKVW, QKVW, bcat + c1 * QKVW,
                        nullptr, 0, qkv2, QKVW, CN2, CHID, nullptr, 0, nullptr };
            gemm_k<<<dim3((CN1 + 127) / 128, 3, 2), 256>>>(j0, j1, 3);
        }

        // both attention directions, one launch; writes normalized agg
        {
            AJob a = { rp12, src12, qkv2, qkv1, prior + c0 * CNH, agg2, CN2 };
            AJob b = { rp21, src21, qkv1, qkv2, prior + c1 * CNH, agg1, CN1 };
            int warps = CN1 + CN2;
            attend_csr<<<(warps * 32 + 255) / 256, 256>>>(a, b);
        }

        // output GEMMs: gelu + gated skip (both types, one launch)
        {
            const float* hold1 = (l == 0) ? h1 : Em;
            const float* hold2 = (l == 0) ? h2 : Ed;
            int ldh = (l == 0) ? CHID : CNL * CHID;
            GJob j0 = { agg1, CHID, Wa + (size_t)c0 * WW, CHID, ba + c0 * CHID,
                        Em + l * CHID, CNL * CHID, nullptr, 0, CN1, CHID, hold1, ldh, skip + c0 };
            GJob j1 = { agg2, CHID, Wa + (size_t)c1 * WW, CHID, ba + c1 * CHID,
                        Ed + l * CHID, CNL * CHID, nullptr, 0, CN2, CHID, hold2, ldh, skip + c1 };
            gemm_k<<<dim3((CN1 + 127) / 128, 1, 2), 256>>>(j0, j1, 2);
        }
    }

    pred_kernel<<<(P * 32 + 255) / 256, 256>>>(pidx, P, out);
}

// round 7
// speedup vs baseline: 1.1652x; 1.0057x over previous
#include <cuda_runtime.h>
#include <cuda_fp16.h>
#include <math.h>

#define CN1 10000
#define CN2 10000
#define CF_IN 256
#define CHID 128
#define CNH 8
#define CDH 16
#define CNL 2
#define QKVW 384
#define EMAX 480000

// ---------------- scratch (static device globals) ----------------
__device__ float  g_h1[CN1 * CHID];
__device__ float  g_h2[CN2 * CHID];
__device__ __half g_qkv1[CN1 * QKVW];
__device__ __half g_qkv2[CN2 * QKVW];
__device__ float  g_agg1[CN1 * CHID], g_agg2[CN2 * CHID];
__device__ float  g_Em[CN1 * CHID * CNL], g_Ed[CN2 * CHID * CNL];
__device__ float  g_Wcat[CNL * 2 * CHID * QKVW];
__device__ float  g_bcat[CNL * 2 * QKVW];
// CSR scratch
__device__ int g_cnt12[CN2], g_cnt21[CN1];
__device__ int g_rp12[CN2 + 1], g_rp21[CN1 + 1];
__device__ int g_cur12[CN2], g_cur21[CN1];
__device__ int g_src12[EMAX], g_src21[EMAX];

// ---------------- helpers ----------------
__device__ __forceinline__ float gelu_f(float x) {
    float x3 = x * x * x;
    return 0.5f * x * (1.0f + tanhf(0.7978845608028654f * (x + 0.044715f * x3)));
}

// ---------------- build packed weights: [128][384] = Wq | Wk@arel | Wv@mrel ----------------
__global__ void prep_cat(const float* __restrict__ Wq, const float* __restrict__ bq,
                         const float* __restrict__ Wk, const float* __restrict__ bk,
                         const float* __restrict__ Wv, const float* __restrict__ bv,
                         const float* __restrict__ arel, const float* __restrict__ mrel) {
    int combo = blockIdx.x;
    const int WW = CHID * CHID;
    float* Wcat = g_Wcat + (size_t)combo * CHID * QKVW;
    float* bcat = g_bcat + combo * QKVW;
    int tid = threadIdx.x;
    for (int i = tid; i < CHID * QKVW; i += blockDim.x) {
        int c = i / QKVW, col = i % QKVW;
        float val;
        if (col < 128) {
            val = Wq[(size_t)combo * WW + c * CHID + col];
        } else if (col < 256) {
            int cc = col - 128, h = cc >> 4, e = cc & 15;
            const float* rel = arel + (size_t)combo * CNH * CDH * CDH + h * CDH * CDH;
            float acc = 0.f;
#pragma unroll
            for (int d = 0; d < CDH; d++)
                acc += Wk[(size_t)combo * WW + c * CHID + h * CDH + d] * rel[d * CDH + e];
            val = acc;
        } else {
            int cc = col - 256, h = cc >> 4, e = cc & 15;
            const float* rel = mrel + (size_t)combo * CNH * CDH * CDH + h * CDH * CDH;
            float acc = 0.f;
#pragma unroll
            for (int d = 0; d < CDH; d++)
                acc += Wv[(size_t)combo * WW + c * CHID + h * CDH + d] * rel[d * CDH + e];
            val = acc;
        }
        Wcat[i] = val;
    }
    if (tid < QKVW) {
        int col = tid;
        float val;
        if (col < 128) {
            val = bq[combo * CHID + col];
        } else if (col < 256) {
            int cc = col - 128, h = cc >> 4, e = cc & 15;
            const float* rel = arel + (size_t)combo * CNH * CDH * CDH + h * CDH * CDH;
            float acc = 0.f;
#pragma unroll
            for (int d = 0; d < CDH; d++) acc += bk[combo * CHID + h * CDH + d] * rel[d * CDH + e];
            val = acc;
        } else {
            int cc = col - 256, h = cc >> 4, e = cc & 15;
            const float* rel = mrel + (size_t)combo * CNH * CDH * CDH + h * CDH * CDH;
            float acc = 0.f;
#pragma unroll
            for (int d = 0; d < CDH; d++) acc += bv[combo * CHID + h * CDH + d] * rel[d * CDH + e];
            val = acc;
        }
        bcat[col] = val;
    }
}

// ---------------- CSR build ----------------
__global__ void csr_zero() {
    int i = blockIdx.x * blockDim.x + threadIdx.x;
    if (i < CN2) g_cnt12[i] = 0;
    if (i < CN1) g_cnt21[i] = 0;
}

__global__ void csr_hist(const int* __restrict__ ei12, const int* __restrict__ ei21, int E) {
    int i = blockIdx.x * blockDim.x + threadIdx.x;
    if (i < E) atomicAdd(&g_cnt12[ei12[E + i]], 1);
    else if (i < 2 * E) { int j = i - E; atomicAdd(&g_cnt21[ei21[E + j]], 1); }
}

// staged-in-smem scan: coalesced global reads/writes
__global__ void __launch_bounds__(1024) csr_scan(int n) {
    int dir = blockIdx.x;
    const int* cnt = dir ? g_cnt21 : g_cnt12;
    int* rp  = dir ? g_rp21 : g_rp12;
    int* cur = dir ? g_cur21 : g_cur12;
    extern __shared__ int sh[];           // n ints staging + 1024 partials
    int* vals = sh;                       // [n]
    int* sums = sh + n;                   // [1024]
    int t = threadIdx.x;
    for (int i = t; i < n; i += 1024) vals[i] = cnt[i];
    __syncthreads();
    int chunk = (n + 1023) / 1024;
    int s0 = t * chunk;
    int local = 0;
    for (int i = 0; i < chunk; i++) if (s0 + i < n) local += vals[s0 + i];
    sums[t] = local;
    __syncthreads();
    for (int off = 1; off < 1024; off <<= 1) {
        int v = (t >= off) ? sums[t - off] : 0;
        __syncthreads();
        sums[t] += v;
        __syncthreads();
    }
    int run = (t == 0) ? 0 : sums[t - 1];
    int total = sums[1023];
    __syncthreads();
    for (int i = 0; i < chunk; i++) if (s0 + i < n) {
        int c = vals[s0 + i];
        vals[s0 + i] = run;
        run += c;
    }
    __syncthreads();
    for (int i = t; i < n; i += 1024) { rp[i] = vals[i]; cur[i] = vals[i]; }
    if (t == 0) rp[n] = total;
}

__global__ void csr_scatter(const int* __restrict__ ei12, const int* __restrict__ ei21, int E) {
    int i = blockIdx.x * blockDim.x + threadIdx.x;
    if (i < E) {
        int dst = ei12[E + i];
        int pos = atomicAdd(&g_cur12[dst], 1);
        g_src12[pos] = ei12[i];
    } else if (i < 2 * E) {
        int j = i - E;
        int dst = ei21[E + j];
        int pos = atomicAdd(&g_cur21[dst], 1);
        g_src21[pos] = ei21[j];
    }
}

// ---------------- GEMM: two jobs per launch (blockIdx.z) ----------------
struct GJob {
    const float* A; int lda;
    const float* B; int ldb;
    const float* bias;
    float* Cf; int ldcf;
    __half* Ch; int ldch;
    int M, K;
    const float* hold; int ldh;
    const float* skipp;
};

// mode 1: Cf = relu(A@B+bias); mode 2: Cf = sg*(gelu(A)@B+bias)+(1-sg)*hold; mode 3: Ch = half(A@B+bias)
__global__ void __launch_bounds__(256)
gemm_k(GJob j0, GJob j1, int mode) {
    GJob jb = blockIdx.z ? j1 : j0;
    __shared__ float As[32][132];
    __shared__ float Bs[32][132];

    int tid = threadIdx.x;
    int tx = tid & 15;
    int ty = tid >> 4;
    int m0 = blockIdx.x * 128;
    int n0 = blockIdx.y * 128;

    float acc[8][8];
#pragma unroll
    for (int i = 0; i < 8; i++)
#pragma unroll
        for (int j = 0; j < 8; j++) acc[i][j] = 0.f;

    for (int k0 = 0; k0 < jb.K; k0 += 32) {
#pragma unroll
        for (int i = 0; i < 4; i++) {
            int lin = tid + i * 256;
            int row = lin >> 3;
            int kc  = (lin & 7) << 2;
            float4 v = make_float4(0.f, 0.f, 0.f, 0.f);
            int m = m0 + row;
            if (m < jb.M) {
                v = *(const float4*)(jb.A + (size_t)m * jb.lda + k0 + kc);
                if (mode == 2) {
                    v.x = gelu_f(v.x); v.y = gelu_f(v.y);
                    v.z = gelu_f(v.z); v.w = gelu_f(v.w);
                }
            }
            As[kc + 0][row] = v.x; As[kc + 1][row] = v.y;
            As[kc + 2][row] = v.z; As[kc + 3][row] = v.w;
        }
#pragma unroll
        for (int i = 0; i < 4; i++) {
            int lin = tid + i * 256;
            int kr = lin >> 5;
            int nc = (lin & 31) << 2;
            *(float4*)&Bs[kr][nc] = *(const float4*)(jb.B + (size_t)(k0 + kr) * jb.ldb + n0 + nc);
        }
        __syncthreads();

#pragma unroll 8
        for (int kk = 0; kk < 32; kk++) {
            float a[8], b[8];
            float4 t0 = *(const float4*)&As[kk][ty * 8];
            float4 t1 = *(const float4*)&As[kk][ty * 8 + 4];
            a[0]=t0.x; a[1]=t0.y; a[2]=t0.z; a[3]=t0.w;
            a[4]=t1.x; a[5]=t1.y; a[6]=t1.z; a[7]=t1.w;
            float4 u0 = *(const float4*)&Bs[kk][tx * 8];
            float4 u1 = *(const float4*)&Bs[kk][tx * 8 + 4];
            b[0]=u0.x; b[1]=u0.y; b[2]=u0.z; b[3]=u0.w;
            b[4]=u1.x; b[5]=u1.y; b[6]=u1.z; b[7]=u1.w;
#pragma unroll
            for (int i = 0; i < 8; i++)
#pragma unroll
                for (int j = 0; j < 8; j++)
                    acc[i][j] += a[i] * b[j];
        }
        __syncthreads();
    }

    float sg = 1.f, sg1 = 0.f;
    if (mode == 2) {
        sg = 1.0f / (1.0f + __expf(-*jb.skipp));
        sg1 = 1.0f - sg;
    }
#pragma unroll
    for (int i = 0; i < 8; i++) {
        int m = m0 + ty * 8 + i;
        if (m >= jb.M) continue;
#pragma unroll
        for (int jj = 0; jj < 2; jj++) {
            int n = tx * 8 + jj * 4;
            float4 r;
            r.x = acc[i][jj * 4 + 0] + jb.bias[n0 + n + 0];
            r.y = acc[i][jj * 4 + 1] + jb.bias[n0 + n + 1];
            r.z = acc[i][jj * 4 + 2] + jb.bias[n0 + n + 2];
            r.w = acc[i][jj * 4 + 3] + jb.bias[n0 + n + 3];
            if (mode == 1) {
                r.x = fmaxf(r.x, 0.f); r.y = fmaxf(r.y, 0.f);
                r.z = fmaxf(r.z, 0.f); r.w = fmaxf(r.w, 0.f);
                *(float4*)(jb.Cf + (size_t)m * jb.ldcf + n0 + n) = r;
            } else if (mode == 2) {
                const float* hp = jb.hold + (size_t)m * jb.ldh + n0 + n;
                r.x = sg * r.x + sg1 * hp[0];
                r.y = sg * r.y + sg1 * hp[1];
                r.z = sg * r.z + sg1 * hp[2];
                r.w = sg * r.w + sg1 * hp[3];
                *(float4*)(jb.Cf + (size_t)m * jb.ldcf + n0 + n) = r;
            } else {
                __half2 p0 = __floats2half2_rn(r.x, r.y);
                __half2 p1 = __floats2half2_rn(r.z, r.w);
                uint2 pk;
                pk.x = *(unsigned*)&p0;
                pk.y = *(unsigned*)&p1;
                *(uint2*)(jb.Ch + (size_t)m * jb.ldch + n0 + n) = pk;
            }
        }
    }
}

// ---------------- CSR attention: warp/dst, 4-edge software pipeline ----------------
struct AJob {
    const int* rp; const int* col;
    const __half* qkv_dst; const __half* qkv_src;
    const float* prior;
    float* agg;
    int n;
};

// one edge's compute given its loaded k/v words
#define EDGE_COMPUTE(kw, vw)                                                      \
    {                                                                             \
        float2 ka = __half22float2(*(__half2*)&(kw).x);                           \
        float2 kb = __half22float2(*(__half2*)&(kw).y);                           \
        float d = qa.x * ka.x + qa.y * ka.y + qb2.x * kb.x + qb2.y * kb.y;        \
        d += __shfl_xor_sync(0xffffffffu, d, 1);                                  \
        d += __shfl_xor_sync(0xffffffffu, d, 2);                                  \
        float e = __expf(d * scale);                                              \
        ssum += e;                                                                \
        float2 va = __half22float2(*(__half2*)&(vw).x);                           \
        float2 vb = __half22float2(*(__half2*)&(vw).y);                           \
        acc0 += e * va.x; acc1 += e * va.y; acc2 += e * vb.x; acc3 += e * vb.y;   \
    }

// k at half-offset 128 = uint2-offset 32; v at half-offset 256 = uint2-offset 64
#define KOFF 32
#define VOFF 64

__global__ void __launch_bounds__(256, 4)
attend_csr(AJob a, AJob b) {
    int gw = (blockIdx.x * blockDim.x + threadIdx.x) >> 5;
    int lane = threadIdx.x & 31;
    int total = a.n + b.n;
    if (gw >= total) return;
    AJob jb = (gw < a.n) ? a : b;
    int dst = (gw < a.n) ? gw : gw - a.n;

    int start = __ldg(jb.rp + dst);
    int end   = __ldg(jb.rp + dst + 1);

    uint2 qw = __ldg((const uint2*)(jb.qkv_dst + (size_t)dst * QKVW) + lane);
    float2 qa = __half22float2(*(__half2*)&qw.x), qb2 = __half22float2(*(__half2*)&qw.y);
    int h = lane >> 2;
    float scale = __ldg(jb.prior + h) * 0.25f;

    float acc0 = 0.f, acc1 = 0.f, acc2 = 0.f, acc3 = 0.f, ssum = 0.f;

    for (int base = start; base < end; base += 32) {
        int myc = (base + lane < end) ? __ldg(jb.col + base + lane) : 0;
        int cnt = min(32, end - base);
        int jj = 0;
        // 4-edge pipelined batches: all 8 loads in flight before any compute
        for (; jj + 4 <= cnt; jj += 4) {
            int s0 = __shfl_sync(0xffffffffu, myc, jj);
            int s1 = __shfl_sync(0xffffffffu, myc, jj + 1);
            int s2 = __shfl_sync(0xffffffffu, myc, jj + 2);
            int s3 = __shfl_sync(0xffffffffu, myc, jj + 3);
            const uint2* p0 = (const uint2*)(jb.qkv_src + (size_t)s0 * QKVW) + lane;
            const uint2* p1 = (const uint2*)(jb.qkv_src + (size_t)s1 * QKVW) + lane;
            const uint2* p2 = (const uint2*)(jb.qkv_src + (size_t)s2 * QKVW) + lane;
            const uint2* p3 = (const uint2*)(jb.qkv_src + (size_t)s3 * QKVW) + lane;
            uint2 k0 = __ldg(p0 + KOFF), v0 = __ldg(p0 + VOFF);
            uint2 k1 = __ldg(p1 + KOFF), v1 = __ldg(p1 + VOFF);
            uint2 k2 = __ldg(p2 + KOFF), v2 = __ldg(p2 + VOFF);
            uint2 k3 = __ldg(p3 + KOFF), v3 = __ldg(p3 + VOFF);
            EDGE_COMPUTE(k0, v0)
            EDGE_COMPUTE(k1, v1)
            EDGE_COMPUTE(k2, v2)
            EDGE_COMPUTE(k3, v3)
        }
        for (; jj < cnt; jj++) {
            int s0 = __shfl_sync(0xffffffffu, myc, jj);
            const uint2* p0 = (const uint2*)(jb.qkv_src + (size_t)s0 * QKVW) + lane;
            uint2 k0 = __ldg(p0 + KOFF), v0 = __ldg(p0 + VOFF);
            EDGE_COMPUTE(k0, v0)
        }
    }

    float inv = 1.0f / (ssum + 1e-16f);
    float4 r = make_float4(acc0 * inv, acc1 * inv, acc2 * inv, acc3 * inv);
    *(float4*)(jb.agg + (size_t)dst * CHID + lane * 4) = r;
}

// ---------------- final pair scores ----------------
__global__ void __launch_bounds__(256)
pred_kernel(const int* __restrict__ pidx, int P, float* __restrict__ out) {
    int warp = (blockIdx.x * blockDim.x + threadIdx.x) >> 5;
    int lane = threadIdx.x & 31;
    if (warp >= P) return;
    int i = pidx[warp];
    int j = pidx[P + warp];
    const float4* em = (const float4*)(g_Em + (size_t)i * (CHID * CNL));
    const float4* ed = (const float4*)(g_Ed + (size_t)j * (CHID * CNL));
    float4 a0 = em[lane],      b0 = ed[lane];
    float4 a1 = em[32 + lane], b1 = ed[32 + lane];
    float d = a0.x * b0.x + a0.y * b0.y + a0.z * b0.z + a0.w * b0.w
            + a1.x * b1.x + a1.y * b1.y + a1.z * b1.z + a1.w * b1.w;
#pragma unroll
    for (int o = 16; o > 0; o >>= 1) d += __shfl_xor_sync(0xffffffffu, d, o);
    if (lane == 0) out[warp] = d;
}

// ---------------- host driver ----------------
extern "C" void kernel_launch(void* const* d_in, const int* in_sizes, int n_in,
                              void* d_out, int out_size) {
    const float* x1    = (const float*)d_in[0];
    const float* x2    = (const float*)d_in[1];
    const int*   ei12  = (const int*)d_in[2];
    const int*   ei21  = (const int*)d_in[3];
    const int*   pidx  = (const int*)d_in[4];
    const float* Win1  = (const float*)d_in[5];
    const float* bin1  = (const float*)d_in[6];
    const float* Win2  = (const float*)d_in[7];
    const float* bin2  = (const float*)d_in[8];
    const float* Wk    = (const float*)d_in[9];
    const float* bk    = (const float*)d_in[10];
    const float* Wq    = (const float*)d_in[11];
    const float* bq    = (const float*)d_in[12];
    const float* Wv    = (const float*)d_in[13];
    const float* bv    = (const float*)d_in[14];
    const float* Wa    = (const float*)d_in[15];
    const float* ba    = (const float*)d_in[16];
    const float* skip  = (const float*)d_in[17];
    const float* arel  = (const float*)d_in[18];
    const float* mrel  = (const float*)d_in[19];
    const float* prior = (const float*)d_in[20];
    float* out = (float*)d_out;

    const int E = in_sizes[2] / 2;
    const int P = in_sizes[4] / 2;

    float *h1, *h2, *agg1, *agg2, *Em, *Ed, *Wcat, *bcat;
    __half *qkv1, *qkv2;
    int *rp12, *rp21, *src12, *src21;
    cudaGetSymbolAddress((void**)&h1,   g_h1);
    cudaGetSymbolAddress((void**)&h2,   g_h2);
    cudaGetSymbolAddress((void**)&qkv1, g_qkv1);
    cudaGetSymbolAddress((void**)&qkv2, g_qkv2);
    cudaGetSymbolAddress((void**)&agg1, g_agg1);
    cudaGetSymbolAddress((void**)&agg2, g_agg2);
    cudaGetSymbolAddress((void**)&Em,   g_Em);
    cudaGetSymbolAddress((void**)&Ed,   g_Ed);
    cudaGetSymbolAddress((void**)&Wcat, g_Wcat);
    cudaGetSymbolAddress((void**)&bcat, g_bcat);
    cudaGetSymbolAddress((void**)&rp12, g_rp12);
    cudaGetSymbolAddress((void**)&rp21, g_rp21);
    cudaGetSymbolAddress((void**)&src12, g_src12);
    cudaGetSymbolAddress((void**)&src21, g_src21);

    const int WW = CHID * CHID;

    prep_cat<<<4, 256>>>(Wq, bq, Wk, bk, Wv, bv, arel, mrel);

    // CSR build (once; reused by both layers)
    csr_zero<<<(CN1 + 255) / 256, 256>>>();
    csr_hist<<<(2 * E + 255) / 256, 256>>>(ei12, ei21, E);
    {
        int shbytes = (CN1 + 1024) * sizeof(int);
        csr_scan<<<2, 1024, shbytes>>>(CN1);
    }
    csr_scatter<<<(2 * E + 255) / 256, 256>>>(ei12, ei21, E);

    // input projections + ReLU (both node types in one launch)
    {
        GJob j0 = { x1, CF_IN, Win1, CHID, bin1, h1, CHID, nullptr, 0, CN1, CF_IN, nullptr, 0, nullptr };
        GJob j1 = { x2, CF_IN, Win2, CHID, bin2, h2, CHID, nullptr, 0, CN2, CF_IN, nullptr, 0, nullptr };
        gemm_k<<<dim3((CN1 + 127) / 128, 1, 2), 256>>>(j0, j1, 1);
    }

    for (int l = 0; l < CNL; l++) {
        const float* A1 = (l == 0) ? h1 : Em;
        const float* A2 = (l == 0) ? h2 : Ed;
        int lda = (l == 0) ? CHID : CNL * CHID;
        int c0 = l * 2 + 0, c1 = l * 2 + 1;

        // fused q|kt|vt projections -> packed half qkv (both types, one launch)
        {
            GJob j0 = { A1, lda, Wcat + (size_t)c0 * CHID * QKVW, QKVW, bcat + c0 * QKVW,
                        nullptr, 0, qkv1, QKVW, CN1, CHID, nullptr, 0, nullptr };
            GJob j1 = { A2, lda, Wcat + (size_t)c1 * CHID * QKVW, QKVW, bcat + c1 * QKVW,
                        nullptr, 0, qkv2, QKVW, CN2, CHID, nullptr, 0, nullptr };
            gemm_k<<<dim3((CN1 + 127) / 128, 3, 2), 256>>>(j0, j1, 3);
        }

        // both attention directions, one launch; writes normalized agg
        {
            AJob a = { rp12, src12, qkv2, qkv1, prior + c0 * CNH, agg2, CN2 };
            AJob b = { rp21, src21, qkv1, qkv2, prior + c1 * CNH, agg1, CN1 };
            int warps = CN1 + CN2;
            attend_csr<<<(warps * 32 + 255) / 256, 256>>>(a, b);
        }

        // output GEMMs: gelu + gated skip (both types, one launch)
        {
            const float* hold1 = (l == 0) ? h1 : Em;
            const float* hold2 = (l == 0) ? h2 : Ed;
            int ldh = (l == 0) ? CHID : CNL * CHID;
            GJob j0 = { agg1, CHID, Wa + (size_t)c0 * WW, CHID, ba + c0 * CHID,
                        Em + l * CHID, CNL * CHID, nullptr, 0, CN1, CHID, hold1, ldh, skip + c0 };
            GJob j1 = { agg2, CHID, Wa + (size_t)c1 * WW, CHID, ba + c1 * CHID,
                        Ed + l * CHID, CNL * CHID, nullptr, 0, CN2, CHID, hold2, ldh, skip + c1 };
            gemm_k<<<dim3((CN1 + 127) / 128, 1, 2), 256>>>(j0, j1, 2);
        }
    }

    pred_kernel<<<(P * 32 + 255) / 256, 256>>>(pidx, P, out);
}

// round 8
// speedup vs baseline: 1.4573x; 1.2507x over previous
#include <cuda_runtime.h>
#include <cuda_fp16.h>
#include <math.h>

#define CN1 10000
#define CN2 10000
#define CF_IN 256
#define CHID 128
#define CNH 8
#define CDH 16
#define CNL 2
#define QKVW 384
#define EMAX 480000

// ---------------- scratch (static device globals) ----------------
__device__ float  g_h1[CN1 * CHID];
__device__ float  g_h2[CN2 * CHID];
__device__ __half g_qkv1[CN1 * QKVW];
__device__ __half g_qkv2[CN2 * QKVW];
__device__ float  g_agg1[CN1 * CHID], g_agg2[CN2 * CHID];
__device__ float  g_Em[CN1 * CHID * CNL], g_Ed[CN2 * CHID * CNL];
__device__ float  g_Wcat[CNL * 2 * CHID * QKVW];
__device__ float  g_bcat[CNL * 2 * QKVW];
// CSR scratch
__device__ int g_cnt12[CN2], g_cnt21[CN1];
__device__ int g_rp12[CN2 + 1], g_rp21[CN1 + 1];
__device__ int g_cur12[CN2], g_cur21[CN1];
__device__ int g_src12[EMAX], g_src21[EMAX];

// ---------------- helpers ----------------
__device__ __forceinline__ float gelu_f(float x) {
    float x3 = x * x * x;
    return 0.5f * x * (1.0f + tanhf(0.7978845608028654f * (x + 0.044715f * x3)));
}

__device__ __forceinline__ unsigned f2tf(float x) {
    unsigned r;
    asm("cvt.rna.tf32.f32 %0, %1;" : "=r"(r) : "f"(x));
    return r;
}

// ---------------- build packed weights: [128][384] = Wq | Wk@arel | Wv@mrel ----------------
__global__ void prep_cat(const float* __restrict__ Wq, const float* __restrict__ bq,
                         const float* __restrict__ Wk, const float* __restrict__ bk,
                         const float* __restrict__ Wv, const float* __restrict__ bv,
                         const float* __restrict__ arel, const float* __restrict__ mrel) {
    int combo = blockIdx.x;
    const int WW = CHID * CHID;
    float* Wcat = g_Wcat + (size_t)combo * CHID * QKVW;
    float* bcat = g_bcat + combo * QKVW;
    int tid = threadIdx.x;
    for (int i = tid; i < CHID * QKVW; i += blockDim.x) {
        int c = i / QKVW, col = i % QKVW;
        float val;
        if (col < 128) {
            val = Wq[(size_t)combo * WW + c * CHID + col];
        } else if (col < 256) {
            int cc = col - 128, h = cc >> 4, e = cc & 15;
            const float* rel = arel + (size_t)combo * CNH * CDH * CDH + h * CDH * CDH;
            float acc = 0.f;
#pragma unroll
            for (int d = 0; d < CDH; d++)
                acc += Wk[(size_t)combo * WW + c * CHID + h * CDH + d] * rel[d * CDH + e];
            val = acc;
        } else {
            int cc = col - 256, h = cc >> 4, e = cc & 15;
            const float* rel = mrel + (size_t)combo * CNH * CDH * CDH + h * CDH * CDH;
            float acc = 0.f;
#pragma unroll
            for (int d = 0; d < CDH; d++)
                acc += Wv[(size_t)combo * WW + c * CHID + h * CDH + d] * rel[d * CDH + e];
            val = acc;
        }
        Wcat[i] = val;
    }
    if (tid < QKVW) {
        int col = tid;
        float val;
        if (col < 128) {
            val = bq[combo * CHID + col];
        } else if (col < 256) {
            int cc = col - 128, h = cc >> 4, e = cc & 15;
            const float* rel = arel + (size_t)combo * CNH * CDH * CDH + h * CDH * CDH;
            float acc = 0.f;
#pragma unroll
            for (int d = 0; d < CDH; d++) acc += bk[combo * CHID + h * CDH + d] * rel[d * CDH + e];
            val = acc;
        } else {
            int cc = col - 256, h = cc >> 4, e = cc & 15;
            const float* rel = mrel + (size_t)combo * CNH * CDH * CDH + h * CDH * CDH;
            float acc = 0.f;
#pragma unroll
            for (int d = 0; d < CDH; d++) acc += bv[combo * CHID + h * CDH + d] * rel[d * CDH + e];
            val = acc;
        }
        bcat[col] = val;
    }
}

// ---------------- CSR build ----------------
__global__ void csr_zero() {
    int i = blockIdx.x * blockDim.x + threadIdx.x;
    if (i < CN2) g_cnt12[i] = 0;
    if (i < CN1) g_cnt21[i] = 0;
}

__global__ void csr_hist(const int* __restrict__ ei12, const int* __restrict__ ei21, int E) {
    int i = blockIdx.x * blockDim.x + threadIdx.x;
    if (i < E) atomicAdd(&g_cnt12[ei12[E + i]], 1);
    else if (i < 2 * E) { int j = i - E; atomicAdd(&g_cnt21[ei21[E + j]], 1); }
}

__global__ void __launch_bounds__(1024) csr_scan(int n) {
    int dir = blockIdx.x;
    const int* cnt = dir ? g_cnt21 : g_cnt12;
    int* rp  = dir ? g_rp21 : g_rp12;
    int* cur = dir ? g_cur21 : g_cur12;
    extern __shared__ int sh[];
    int* vals = sh;
    int* sums = sh + n;
    int t = threadIdx.x;
    for (int i = t; i < n; i += 1024) vals[i] = cnt[i];
    __syncthreads();
    int chunk = (n + 1023) / 1024;
    int s0 = t * chunk;
    int local = 0;
    for (int i = 0; i < chunk; i++) if (s0 + i < n) local += vals[s0 + i];
    sums[t] = local;
    __syncthreads();
    for (int off = 1; off < 1024; off <<= 1) {
        int v = (t >= off) ? sums[t - off] : 0;
        __syncthreads();
        sums[t] += v;
        __syncthreads();
    }
    int run = (t == 0) ? 0 : sums[t - 1];
    int total = sums[1023];
    __syncthreads();
    for (int i = 0; i < chunk; i++) if (s0 + i < n) {
        int c = vals[s0 + i];
        vals[s0 + i] = run;
        run += c;
    }
    __syncthreads();
    for (int i = t; i < n; i += 1024) { rp[i] = vals[i]; cur[i] = vals[i]; }
    if (t == 0) rp[n] = total;
}

__global__ void csr_scatter(const int* __restrict__ ei12, const int* __restrict__ ei21, int E) {
    int i = blockIdx.x * blockDim.x + threadIdx.x;
    if (i < E) {
        int dst = ei12[E + i];
        int pos = atomicAdd(&g_cur12[dst], 1);
        g_src12[pos] = ei12[i];
    } else if (i < 2 * E) {
        int j = i - E;
        int dst = ei21[E + j];
        int pos = atomicAdd(&g_cur21[dst], 1);
        g_src21[pos] = ei21[j];
    }
}

// ---------------- TF32 tensor-core GEMM: two jobs per launch (blockIdx.z) ----------------
struct GJob {
    const float* A; int lda;
    const float* B; int ldb;
    const float* bias;
    float* Cf; int ldcf;
    __half* Ch; int ldch;
    int M, K;
    const float* hold; int ldh;
    const float* skipp;
};

// mode 1: Cf = relu(A@B+bias); mode 2: Cf = sg*(gelu(A)@B+bias)+(1-sg)*hold; mode 3: Ch = half(A@B+bias)
// Block tile 128x128, BK=32, 256 threads = 8 warps in 2(M)x4(N); warp tile 64x32;
// per warp: 4x4 grid of m16n8k8 tf32 mma.
__global__ void __launch_bounds__(256)
gemm_tc(GJob j0, GJob j1, int mode) {
    GJob jb = blockIdx.z ? j1 : j0;
    __shared__ unsigned As[128][36];    // [m][k], pad 36 (conflict-free frags & stores)
    __shared__ unsigned Bs[32][136];    // [k][n], pad 136

    int tid  = threadIdx.x;
    int warp = tid >> 5;
    int lane = tid & 31;
    int g = lane >> 2;        // groupID 0..7
    int c = lane & 3;         // threadID in group 0..3
    int warp_m = warp >> 2;   // 0..1
    int warp_n = warp & 3;    // 0..3
    int m0 = blockIdx.x * 128;
    int n0 = blockIdx.y * 128;

    float acc[4][4][4];
#pragma unroll
    for (int mi = 0; mi < 4; mi++)
#pragma unroll
        for (int ni = 0; ni < 4; ni++)
#pragma unroll
            for (int r = 0; r < 4; r++) acc[mi][ni][r] = 0.f;

    for (int k0 = 0; k0 < jb.K; k0 += 32) {
        // A tile: 128x32 f32 -> tf32 bits, [m][k]
#pragma unroll
        for (int i = 0; i < 4; i++) {
            int lin = tid + i * 256;
            int row = lin >> 3;
            int kc4 = (lin & 7) << 2;
            float4 v = make_float4(0.f, 0.f, 0.f, 0.f);
            int m = m0 + row;
            if (m < jb.M) {
                v = *(const float4*)(jb.A + (size_t)m * jb.lda + k0 + kc4);
                if (mode == 2) {
                    v.x = gelu_f(v.x); v.y = gelu_f(v.y);
                    v.z = gelu_f(v.z); v.w = gelu_f(v.w);
                }
            }
            uint4 t;
            t.x = f2tf(v.x); t.y = f2tf(v.y); t.z = f2tf(v.z); t.w = f2tf(v.w);
            *(uint4*)&As[row][kc4] = t;
        }
        // B tile: 32x128, [k][n]
#pragma unroll
        for (int i = 0; i < 4; i++) {
            int lin = tid + i * 256;
            int kr  = lin >> 5;
            int nc4 = (lin & 31) << 2;
            float4 v = *(const float4*)(jb.B + (size_t)(k0 + kr) * jb.ldb + n0 + nc4);
            uint4 t;
            t.x = f2tf(v.x); t.y = f2tf(v.y); t.z = f2tf(v.z); t.w = f2tf(v.w);
            *(uint4*)&Bs[kr][nc4] = t;
        }
        __syncthreads();

#pragma unroll
        for (int ks = 0; ks < 4; ks++) {
            int kk = ks * 8;
            unsigned a[4][4];
#pragma unroll
            for (int mi = 0; mi < 4; mi++) {
                int r0 = warp_m * 64 + mi * 16 + g;
                a[mi][0] = As[r0][kk + c];
                a[mi][1] = As[r0 + 8][kk + c];
                a[mi][2] = As[r0][kk + c + 4];
                a[mi][3] = As[r0 + 8][kk + c + 4];
            }
            unsigned b[4][2];
#pragma unroll
            for (int ni = 0; ni < 4; ni++) {
                int nn = warp_n * 32 + ni * 8 + g;
                b[ni][0] = Bs[kk + c][nn];
                b[ni][1] = Bs[kk + c + 4][nn];
            }
#pragma unroll
            for (int mi = 0; mi < 4; mi++)
#pragma unroll
                for (int ni = 0; ni < 4; ni++) {
                    asm volatile(
                        "mma.sync.aligned.m16n8k8.row.col.f32.tf32.tf32.f32 "
                        "{%0,%1,%2,%3}, {%4,%5,%6,%7}, {%8,%9}, {%0,%1,%2,%3};\n"
                        : "+f"(acc[mi][ni][0]), "+f"(acc[mi][ni][1]),
                          "+f"(acc[mi][ni][2]), "+f"(acc[mi][ni][3])
                        : "r"(a[mi][0]), "r"(a[mi][1]), "r"(a[mi][2]), "r"(a[mi][3]),
                          "r"(b[ni][0]), "r"(b[ni][1]));
                }
        }
        __syncthreads();
    }

    float sg = 1.f, sg1 = 0.f;
    if (mode == 2) {
        sg = 1.0f / (1.0f + __expf(-*jb.skipp));
        sg1 = 1.0f - sg;
    }

#pragma unroll
    for (int mi = 0; mi < 4; mi++) {
#pragma unroll
        for (int half = 0; half < 2; half++) {     // c0,c1 then c2,c3 (row +8)
            int r = m0 + warp_m * 64 + mi * 16 + g + half * 8;
            if (r >= jb.M) continue;
#pragma unroll
            for (int ni = 0; ni < 4; ni++) {
                int n = n0 + warp_n * 32 + ni * 8 + 2 * c;
                float x0 = acc[mi][ni][half * 2 + 0] + jb.bias[n + 0];
                float x1 = acc[mi][ni][half * 2 + 1] + jb.bias[n + 1];
                if (mode == 1) {
                    x0 = fmaxf(x0, 0.f); x1 = fmaxf(x1, 0.f);
                    float2 w = make_float2(x0, x1);
                    *(float2*)(jb.Cf + (size_t)r * jb.ldcf + n) = w;
                } else if (mode == 2) {
                    const float* hp = jb.hold + (size_t)r * jb.ldh + n;
                    float2 w = make_float2(sg * x0 + sg1 * hp[0], sg * x1 + sg1 * hp[1]);
                    *(float2*)(jb.Cf + (size_t)r * jb.ldcf + n) = w;
                } else {
                    __half2 p = __floats2half2_rn(x0, x1);
                    *(__half2*)(jb.Ch + (size_t)r * jb.ldch + n) = p;
                }
            }
        }
    }
}

// ---------------- CSR attention: warp/dst, 4-edge software pipeline (unchanged from R7) ----------------
struct AJob {
    const int* rp; const int* col;
    const __half* qkv_dst; const __half* qkv_src;
    const float* prior;
    float* agg;
    int n;
};

#define EDGE_COMPUTE(kw, vw)                                                      \
    {                                                                             \
        float2 ka = __half22float2(*(__half2*)&(kw).x);                           \
        float2 kb = __half22float2(*(__half2*)&(kw).y);                           \
        float d = qa.x * ka.x + qa.y * ka.y + qb2.x * kb.x + qb2.y * kb.y;        \
        d += __shfl_xor_sync(0xffffffffu, d, 1);                                  \
        d += __shfl_xor_sync(0xffffffffu, d, 2);                                  \
        float e = __expf(d * scale);                                              \
        ssum += e;                                                                \
        float2 va = __half22float2(*(__half2*)&(vw).x);                           \
        float2 vb = __half22float2(*(__half2*)&(vw).y);                           \
        acc0 += e * va.x; acc1 += e * va.y; acc2 += e * vb.x; acc3 += e * vb.y;   \
    }

#define KOFF 32
#define VOFF 64

__global__ void __launch_bounds__(256, 4)
attend_csr(AJob a, AJob b) {
    int gw = (blockIdx.x * blockDim.x + threadIdx.x) >> 5;
    int lane = threadIdx.x & 31;
    int total = a.n + b.n;
    if (gw >= total) return;
    AJob jb = (gw < a.n) ? a : b;
    int dst = (gw < a.n) ? gw : gw - a.n;

    int start = __ldg(jb.rp + dst);
    int end   = __ldg(jb.rp + dst + 1);

    uint2 qw = __ldg((const uint2*)(jb.qkv_dst + (size_t)dst * QKVW) + lane);
    float2 qa = __half22float2(*(__half2*)&qw.x), qb2 = __half22float2(*(__half2*)&qw.y);
    int h = lane >> 2;
    float scale = __ldg(jb.prior + h) * 0.25f;

    float acc0 = 0.f, acc1 = 0.f, acc2 = 0.f, acc3 = 0.f, ssum = 0.f;

    for (int base = start; base < end; base += 32) {
        int myc = (base + lane < end) ? __ldg(jb.col + base + lane) : 0;
        int cnt = min(32, end - base);
        int jj = 0;
        for (; jj + 4 <= cnt; jj += 4) {
            int s0 = __shfl_sync(0xffffffffu, myc, jj);
            int s1 = __shfl_sync(0xffffffffu, myc, jj + 1);
            int s2 = __shfl_sync(0xffffffffu, myc, jj + 2);
            int s3 = __shfl_sync(0xffffffffu, myc, jj + 3);
            const uint2* p0 = (const uint2*)(jb.qkv_src + (size_t)s0 * QKVW) + lane;
            const uint2* p1 = (const uint2*)(jb.qkv_src + (size_t)s1 * QKVW) + lane;
            const uint2* p2 = (const uint2*)(jb.qkv_src + (size_t)s2 * QKVW) + lane;
            const uint2* p3 = (const uint2*)(jb.qkv_src + (size_t)s3 * QKVW) + lane;
            uint2 k0 = __ldg(p0 + KOFF), v0 = __ldg(p0 + VOFF);
            uint2 k1 = __ldg(p1 + KOFF), v1 = __ldg(p1 + VOFF);
            uint2 k2 = __ldg(p2 + KOFF), v2 = __ldg(p2 + VOFF);
            uint2 k3 = __ldg(p3 + KOFF), v3 = __ldg(p3 + VOFF);
            EDGE_COMPUTE(k0, v0)
            EDGE_COMPUTE(k1, v1)
            EDGE_COMPUTE(k2, v2)
            EDGE_COMPUTE(k3, v3)
        }
        for (; jj < cnt; jj++) {
            int s0 = __shfl_sync(0xffffffffu, myc, jj);
            const uint2* p0 = (const uint2*)(jb.qkv_src + (size_t)s0 * QKVW) + lane;
            uint2 k0 = __ldg(p0 + KOFF), v0 = __ldg(p0 + VOFF);
            EDGE_COMPUTE(k0, v0)
        }
    }

    float inv = 1.0f / (ssum + 1e-16f);
    float4 r = make_float4(acc0 * inv, acc1 * inv, acc2 * inv, acc3 * inv);
    *(float4*)(jb.agg + (size_t)dst * CHID + lane * 4) = r;
}

// ---------------- final pair scores ----------------
__global__ void __launch_bounds__(256)
pred_kernel(const int* __restrict__ pidx, int P, float* __restrict__ out) {
    int warp = (blockIdx.x * blockDim.x + threadIdx.x) >> 5;
    int lane = threadIdx.x & 31;
    if (warp >= P) return;
    int i = pidx[warp];
    int j = pidx[P + warp];
    const float4* em = (const float4*)(g_Em + (size_t)i * (CHID * CNL));
    const float4* ed = (const float4*)(g_Ed + (size_t)j * (CHID * CNL));
    float4 a0 = em[lane],      b0 = ed[lane];
    float4 a1 = em[32 + lane], b1 = ed[32 + lane];
    float d = a0.x * b0.x + a0.y * b0.y + a0.z * b0.z + a0.w * b0.w
            + a1.x * b1.x + a1.y * b1.y + a1.z * b1.z + a1.w * b1.w;
#pragma unroll
    for (int o = 16; o > 0; o >>= 1) d += __shfl_xor_sync(0xffffffffu, d, o);
    if (lane == 0) out[warp] = d;
}

// ---------------- host driver ----------------
extern "C" void kernel_launch(void* const* d_in, const int* in_sizes, int n_in,
                              void* d_out, int out_size) {
    const float* x1    = (const float*)d_in[0];
    const float* x2    = (const float*)d_in[1];
    const int*   ei12  = (const int*)d_in[2];
    const int*   ei21  = (const int*)d_in[3];
    const int*   pidx  = (const int*)d_in[4];
    const float* Win1  = (const float*)d_in[5];
    const float* bin1  = (const float*)d_in[6];
    const float* Win2  = (const float*)d_in[7];
    const float* bin2  = (const float*)d_in[8];
    const float* Wk    = (const float*)d_in[9];
    const float* bk    = (const float*)d_in[10];
    const float* Wq    = (const float*)d_in[11];
    const float* bq    = (const float*)d_in[12];
    const float* Wv    = (const float*)d_in[13];
    const float* bv    = (const float*)d_in[14];
    const float* Wa    = (const float*)d_in[15];
    const float* ba    = (const float*)d_in[16];
    const float* skip  = (const float*)d_in[17];
    const float* arel  = (const float*)d_in[18];
    const float* mrel  = (const float*)d_in[19];
    const float* prior = (const float*)d_in[20];
    float* out = (float*)d_out;

    const int E = in_sizes[2] / 2;
    const int P = in_sizes[4] / 2;

    float *h1, *h2, *agg1, *agg2, *Em, *Ed, *Wcat, *bcat;
    __half *qkv1, *qkv2;
    int *rp12, *rp21, *src12, *src21;
    cudaGetSymbolAddress((void**)&h1,   g_h1);
    cudaGetSymbolAddress((void**)&h2,   g_h2);
    cudaGetSymbolAddress((void**)&qkv1, g_qkv1);
    cudaGetSymbolAddress((void**)&qkv2, g_qkv2);
    cudaGetSymbolAddress((void**)&agg1, g_agg1);
    cudaGetSymbolAddress((void**)&agg2, g_agg2);
    cudaGetSymbolAddress((void**)&Em,   g_Em);
    cudaGetSymbolAddress((void**)&Ed,   g_Ed);
    cudaGetSymbolAddress((void**)&Wcat, g_Wcat);
    cudaGetSymbolAddress((void**)&bcat, g_bcat);
    cudaGetSymbolAddress((void**)&rp12, g_rp12);
    cudaGetSymbolAddress((void**)&rp21, g_rp21);
    cudaGetSymbolAddress((void**)&src12, g_src12);
    cudaGetSymbolAddress((void**)&src21, g_src21);

    const int WW = CHID * CHID;

    prep_cat<<<4, 256>>>(Wq, bq, Wk, bk, Wv, bv, arel, mrel);

    // CSR build (once; reused by both layers)
    csr_zero<<<(CN1 + 255) / 256, 256>>>();
    csr_hist<<<(2 * E + 255) / 256, 256>>>(ei12, ei21, E);
    {
        int shbytes = (CN1 + 1024) * sizeof(int);
        csr_scan<<<2, 1024, shbytes>>>(CN1);
    }
    csr_scatter<<<(2 * E + 255) / 256, 256>>>(ei12, ei21, E);

    // input projections + ReLU (both node types in one launch)
    {
        GJob j0 = { x1, CF_IN, Win1, CHID, bin1, h1, CHID, nullptr, 0, CN1, CF_IN, nullptr, 0, nullptr };
        GJob j1 = { x2, CF_IN, Win2, CHID, bin2, h2, CHID, nullptr, 0, CN2, CF_IN, nullptr, 0, nullptr };
        gemm_tc<<<dim3((CN1 + 127) / 128, 1, 2), 256>>>(j0, j1, 1);
    }

    for (int l = 0; l < CNL; l++) {
        const float* A1 = (l == 0) ? h1 : Em;
        const float* A2 = (l == 0) ? h2 : Ed;
        int lda = (l == 0) ? CHID : CNL * CHID;
        int c0 = l * 2 + 0, c1 = l * 2 + 1;

        // fused q|kt|vt projections -> packed half qkv (both types, one launch)
        {
            GJob j0 = { A1, lda, Wcat + (size_t)c0 * CHID * QKVW, QKVW, bcat + c0 * QKVW,
                        nullptr, 0, qkv1, QKVW, CN1, CHID, nullptr, 0, nullptr };
            GJob j1 = { A2, lda, Wcat + (size_t)c1 * CHID * QKVW, QKVW, bcat + c1 * QKVW,
                        nullptr, 0, qkv2, QKVW, CN2, CHID, nullptr, 0, nullptr };
            gemm_tc<<<dim3((CN1 + 127) / 128, 3, 2), 256>>>(j0, j1, 3);
        }

        // both attention directions, one launch; writes normalized agg
        {
            AJob a = { rp12, src12, qkv2, qkv1, prior + c0 * CNH, agg2, CN2 };
            AJob b = { rp21, src21, qkv1, qkv2, prior + c1 * CNH, agg1, CN1 };
            int warps = CN1 + CN2;
            attend_csr<<<(warps * 32 + 255) / 256, 256>>>(a, b);
        }

        // output GEMMs: gelu + gated skip (both types, one launch)
        {
            const float* hold1 = (l == 0) ? h1 : Em;
            const float* hold2 = (l == 0) ? h2 : Ed;
            int ldh = (l == 0) ? CHID : CNL * CHID;
            GJob j0 = { agg1, CHID, Wa + (size_t)c0 * WW, CHID, ba + c0 * CHID,
                        Em + l * CHID, CNL * CHID, nullptr, 0, CN1, CHID, hold1, ldh, skip + c0 };
            GJob j1 = { agg2, CHID, Wa + (size_t)c1 * WW, CHID, ba + c1 * CHID,
                        Ed + l * CHID, CNL * CHID, nullptr, 0, CN2, CHID, hold2, ldh, skip + c1 };
            gemm_tc<<<dim3((CN1 + 127) / 128, 1, 2), 256>>>(j0, j1, 2);
        }
    }

    pred_kernel<<<(P * 32 + 255) / 256, 256>>>(pidx, P, out);
}

// round 11
// speedup vs baseline: 1.4805x; 1.0159x over previous
#include <cuda_runtime.h>
#include <cuda_fp16.h>
#include <math.h>

#define CN1 10000
#define CN2 10000
#define CF_IN 256
#define CHID 128
#define CNH 8
#define CDH 16
#define CNL 2
#define QKVW 384
#define EMAX 480000

// ---------------- scratch (static device globals) ----------------
__device__ float  g_h1[CN1 * CHID];
__device__ float  g_h2[CN2 * CHID];
__device__ __half g_qkv1[CN1 * QKVW];
__device__ __half g_qkv2[CN2 * QKVW];
__device__ float  g_agg1[CN1 * CHID], g_agg2[CN2 * CHID];
__device__ float  g_Em[CN1 * CHID * CNL], g_Ed[CN2 * CHID * CNL];
__device__ float  g_Wcat[CNL * 2 * CHID * QKVW];
__device__ float  g_bcat[CNL * 2 * QKVW];
// CSR scratch
__device__ int g_cnt12[CN2], g_cnt21[CN1];
__device__ int g_rp12[CN2 + 1], g_rp21[CN1 + 1];
__device__ int g_cur12[CN2], g_cur21[CN1];
__device__ int g_src12[EMAX], g_src21[EMAX];

// ---------------- helpers ----------------
__device__ __forceinline__ float gelu_f(float x) {
    float x3 = x * x * x;
    return 0.5f * x * (1.0f + tanhf(0.7978845608028654f * (x + 0.044715f * x3)));
}

__device__ __forceinline__ unsigned f2tf(float x) {
    unsigned r;
    asm("cvt.rna.tf32.f32 %0, %1;" : "=r"(r) : "f"(x));
    return r;
}

__device__ __forceinline__ void unpack8(uint4 w, float* f) {
    float2 t;
    t = __half22float2(*(__half2*)&w.x); f[0] = t.x; f[1] = t.y;
    t = __half22float2(*(__half2*)&w.y); f[2] = t.x; f[3] = t.y;
    t = __half22float2(*(__half2*)&w.z); f[4] = t.x; f[5] = t.y;
    t = __half22float2(*(__half2*)&w.w); f[6] = t.x; f[7] = t.y;
}

// ---------------- build packed weights (+ zero CSR counters in extra blocks) ----------------
__global__ void prep_cat(const float* __restrict__ Wq, const float* __restrict__ bq,
                         const float* __restrict__ Wk, const float* __restrict__ bk,
                         const float* __restrict__ Wv, const float* __restrict__ bv,
                         const float* __restrict__ arel, const float* __restrict__ mrel) {
    if (blockIdx.x >= 4) {
        int i = (blockIdx.x - 4) * blockDim.x + threadIdx.x;
        if (i < CN2) g_cnt12[i] = 0;
        if (i < CN1) g_cnt21[i] = 0;
        return;
    }
    int combo = blockIdx.x;
    const int WW = CHID * CHID;
    float* Wcat = g_Wcat + (size_t)combo * CHID * QKVW;
    float* bcat = g_bcat + combo * QKVW;
    int tid = threadIdx.x;
    for (int i = tid; i < CHID * QKVW; i += blockDim.x) {
        int c = i / QKVW, col = i % QKVW;
        float val;
        if (col < 128) {
            val = Wq[(size_t)combo * WW + c * CHID + col];
        } else if (col < 256) {
            int cc = col - 128, h = cc >> 4, e = cc & 15;
            const float* rel = arel + (size_t)combo * CNH * CDH * CDH + h * CDH * CDH;
            float acc = 0.f;
#pragma unroll
            for (int d = 0; d < CDH; d++)
                acc += Wk[(size_t)combo * WW + c * CHID + h * CDH + d] * rel[d * CDH + e];
            val = acc;
        } else {
            int cc = col - 256, h = cc >> 4, e = cc & 15;
            const float* rel = mrel + (size_t)combo * CNH * CDH * CDH + h * CDH * CDH;
            float acc = 0.f;
#pragma unroll
            for (int d = 0; d < CDH; d++)
                acc += Wv[(size_t)combo * WW + c * CHID + h * CDH + d] * rel[d * CDH + e];
            val = acc;
        }
        Wcat[i] = val;
    }
    if (tid < QKVW) {
        int col = tid;
        float val;
        if (col < 128) {
            val = bq[combo * CHID + col];
        } else if (col < 256) {
            int cc = col - 128, h = cc >> 4, e = cc & 15;
            const float* rel = arel + (size_t)combo * CNH * CDH * CDH + h * CDH * CDH;
            float acc = 0.f;
#pragma unroll
            for (int d = 0; d < CDH; d++) acc += bk[combo * CHID + h * CDH + d] * rel[d * CDH + e];
            val = acc;
        } else {
            int cc = col - 256, h = cc >> 4, e = cc & 15;
            const float* rel = mrel + (size_t)combo * CNH * CDH * CDH + h * CDH * CDH;
            float acc = 0.f;
#pragma unroll
            for (int d = 0; d < CDH; d++) acc += bv[combo * CHID + h * CDH + d] * rel[d * CDH + e];
            val = acc;
        }
        bcat[col] = val;
    }
}

// ---------------- CSR build ----------------
__global__ void csr_hist(const int* __restrict__ ei12, const int* __restrict__ ei21, int E) {
    int i = blockIdx.x * blockDim.x + threadIdx.x;
    if (i < E) atomicAdd(&g_cnt12[ei12[E + i]], 1);
    else if (i < 2 * E) { int j = i - E; atomicAdd(&g_cnt21[ei21[E + j]], 1); }
}

__global__ void __launch_bounds__(1024) csr_scan(int n) {
    int dir = blockIdx.x;
    const int* cnt = dir ? g_cnt21 : g_cnt12;
    int* rp  = dir ? g_rp21 : g_rp12;
    int* cur = dir ? g_cur21 : g_cur12;
    extern __shared__ int sh[];
    int* vals = sh;
    int* sums = sh + n;
    int t = threadIdx.x;
    for (int i = t; i < n; i += 1024) vals[i] = cnt[i];
    __syncthreads();
    int chunk = (n + 1023) / 1024;
    int s0 = t * chunk;
    int local = 0;
    for (int i = 0; i < chunk; i++) if (s0 + i < n) local += vals[s0 + i];
    sums[t] = local;
    __syncthreads();
    for (int off = 1; off < 1024; off <<= 1) {
        int v = (t >= off) ? sums[t - off] : 0;
        __syncthreads();
        sums[t] += v;
        __syncthreads();
    }
    int run = (t == 0) ? 0 : sums[t - 1];
    int total = sums[1023];
    __syncthreads();
    for (int i = 0; i < chunk; i++) if (s0 + i < n) {
        int c = vals[s0 + i];
        vals[s0 + i] = run;
        run += c;
    }
    __syncthreads();
    for (int i = t; i < n; i += 1024) { rp[i] = vals[i]; cur[i] = vals[i]; }
    if (t == 0) rp[n] = total;
}

__global__ void csr_scatter(const int* __restrict__ ei12, const int* __restrict__ ei21, int E) {
    int i = blockIdx.x * blockDim.x + threadIdx.x;
    if (i < E) {
        int dst = ei12[E + i];
        int pos = atomicAdd(&g_cur12[dst], 1);
        g_src12[pos] = ei12[i];
    } else if (i < 2 * E) {
        int j = i - E;
        int dst = ei21[E + j];
        int pos = atomicAdd(&g_cur21[dst], 1);
        g_src21[pos] = ei21[j];
    }
}

// ---------------- TF32 tensor-core GEMM: two jobs per launch (blockIdx.z) ----------------
struct GJob {
    const float* A; int lda;
    const float* B; int ldb;
    const float* bias;
    float* Cf; int ldcf;
    __half* Ch; int ldch;
    int M, K;
    const float* hold; int ldh;
    const float* skipp;
};

__global__ void __launch_bounds__(256)
gemm_tc(GJob j0, GJob j1, int mode) {
    GJob jb = blockIdx.z ? j1 : j0;
    __shared__ unsigned As[128][36];
    __shared__ unsigned Bs[32][136];

    int tid  = threadIdx.x;
    int warp = tid >> 5;
    int lane = tid & 31;
    int g = lane >> 2;
    int c = lane & 3;
    int warp_m = warp >> 2;
    int warp_n = warp & 3;
    int m0 = blockIdx.x * 128;
    int n0 = blockIdx.y * 128;

    float acc[4][4][4];
#pragma unroll
    for (int mi = 0; mi < 4; mi++)
#pragma unroll
        for (int ni = 0; ni < 4; ni++)
#pragma unroll
            for (int r = 0; r < 4; r++) acc[mi][ni][r] = 0.f;

    for (int k0 = 0; k0 < jb.K; k0 += 32) {
#pragma unroll
        for (int i = 0; i < 4; i++) {
            int lin = tid + i * 256;
            int row = lin >> 3;
            int kc4 = (lin & 7) << 2;
            float4 v = make_float4(0.f, 0.f, 0.f, 0.f);
            int m = m0 + row;
            if (m < jb.M) {
                v = *(const float4*)(jb.A + (size_t)m * jb.lda + k0 + kc4);
                if (mode == 2) {
                    v.x = gelu_f(v.x); v.y = gelu_f(v.y);
                    v.z = gelu_f(v.z); v.w = gelu_f(v.w);
                }
            }
            uint4 t;
            t.x = f2tf(v.x); t.y = f2tf(v.y); t.z = f2tf(v.z); t.w = f2tf(v.w);
            *(uint4*)&As[row][kc4] = t;
        }
#pragma unroll
        for (int i = 0; i < 4; i++) {
            int lin = tid + i * 256;
            int kr  = lin >> 5;
            int nc4 = (lin & 31) << 2;
            float4 v = *(const float4*)(jb.B + (size_t)(k0 + kr) * jb.ldb + n0 + nc4);
            uint4 t;
            t.x = f2tf(v.x); t.y = f2tf(v.y); t.z = f2tf(v.z); t.w = f2tf(v.w);
            *(uint4*)&Bs[kr][nc4] = t;
        }
        __syncthreads();

#pragma unroll
        for (int ks = 0; ks < 4; ks++) {
            int kk = ks * 8;
            unsigned a[4][4];
#pragma unroll
            for (int mi = 0; mi < 4; mi++) {
                int r0 = warp_m * 64 + mi * 16 + g;
                a[mi][0] = As[r0][kk + c];
                a[mi][1] = As[r0 + 8][kk + c];
                a[mi][2] = As[r0][kk + c + 4];
                a[mi][3] = As[r0 + 8][kk + c + 4];
            }
            unsigned b[4][2];
#pragma unroll
            for (int ni = 0; ni < 4; ni++) {
                int nn = warp_n * 32 + ni * 8 + g;
                b[ni][0] = Bs[kk + c][nn];
                b[ni][1] = Bs[kk + c + 4][nn];
            }
#pragma unroll
            for (int mi = 0; mi < 4; mi++)
#pragma unroll
                for (int ni = 0; ni < 4; ni++) {
                    asm volatile(
                        "mma.sync.aligned.m16n8k8.row.col.f32.tf32.tf32.f32 "
                        "{%0,%1,%2,%3}, {%4,%5,%6,%7}, {%8,%9}, {%0,%1,%2,%3};\n"
                        : "+f"(acc[mi][ni][0]), "+f"(acc[mi][ni][1]),
                          "+f"(acc[mi][ni][2]), "+f"(acc[mi][ni][3])
                        : "r"(a[mi][0]), "r"(a[mi][1]), "r"(a[mi][2]), "r"(a[mi][3]),
                          "r"(b[ni][0]), "r"(b[ni][1]));
                }
        }
        __syncthreads();
    }

    float sg = 1.f, sg1 = 0.f;
    if (mode == 2) {
        sg = 1.0f / (1.0f + __expf(-*jb.skipp));
        sg1 = 1.0f - sg;
    }

#pragma unroll
    for (int mi = 0; mi < 4; mi++) {
#pragma unroll
        for (int half = 0; half < 2; half++) {
            int r = m0 + warp_m * 64 + mi * 16 + g + half * 8;
            if (r >= jb.M) continue;
#pragma unroll
            for (int ni = 0; ni < 4; ni++) {
                int n = n0 + warp_n * 32 + ni * 8 + 2 * c;
                float x0 = acc[mi][ni][half * 2 + 0] + jb.bias[n + 0];
                float x1 = acc[mi][ni][half * 2 + 1] + jb.bias[n + 1];
                if (mode == 1) {
                    x0 = fmaxf(x0, 0.f); x1 = fmaxf(x1, 0.f);
                    *(float2*)(jb.Cf + (size_t)r * jb.ldcf + n) = make_float2(x0, x1);
                } else if (mode == 2) {
                    const float* hp = jb.hold + (size_t)r * jb.ldh + n;
                    *(float2*)(jb.Cf + (size_t)r * jb.ldcf + n) =
                        make_float2(sg * x0 + sg1 * hp[0], sg * x1 + sg1 * hp[1]);
                } else {
                    __half2 p = __floats2half2_rn(x0, x1);
                    *(__half2*)(jb.Ch + (size_t)r * jb.ldch + n) = p;
                }
            }
        }
    }
}

// ---------------- CSR attention: warp = 1 dst, two 16-lane edge teams ----------------
struct AJob {
    const int* rp; const int* col;
    const __half* qkv_dst; const __half* qkv_src;
    const float* prior;
    float* agg;
    int n;
};

__device__ __forceinline__ void team_edge(uint4 kw, uint4 vw, bool valid,
                                          const float* qf, float scale,
                                          float* acc, float& ssum) {
    float kf[8]; unpack8(kw, kf);
    float d = 0.f;
#pragma unroll
    for (int i = 0; i < 8; i++) d += qf[i] * kf[i];
    d += __shfl_xor_sync(0xffffffffu, d, 1);   // complete 16-dim head dot (lane pairs)
    float e = valid ? __expf(d * scale) : 0.f;
    ssum += e;
    float vf[8]; unpack8(vw, vf);
#pragma unroll
    for (int i = 0; i < 8; i++) acc[i] += e * vf[i];
}

__global__ void __launch_bounds__(256, 4)
attend_csr(AJob a, AJob b) {
    int gw = (blockIdx.x * blockDim.x + threadIdx.x) >> 5;
    int lane = threadIdx.x & 31;
    int tlane = lane & 15;
    int team  = lane >> 4;
    int total = a.n + b.n;
    if (gw >= total) return;
    AJob jb = (gw < a.n) ? a : b;
    int dst = (gw < a.n) ? gw : gw - a.n;

    int start = __ldg(jb.rp + dst);
    int end   = __ldg(jb.rp + dst + 1);

    // q: lane holds halfs [8*tlane, 8*tlane+8) = half of head (tlane>>1)
    uint4 qw = __ldg((const uint4*)(jb.qkv_dst + (size_t)dst * QKVW) + tlane);
    float qf[8]; unpack8(qw, qf);
    int h = tlane >> 1;
    float scale = __ldg(jb.prior + h) * 0.25f;

    float acc[8];
#pragma unroll
    for (int i = 0; i < 8; i++) acc[i] = 0.f;
    float ssum = 0.f;

    for (int base = start; base < end; base += 32) {
        int myc = (base + lane < end) ? __ldg(jb.col + base + lane) : 0;
        int cnt = min(32, end - base);
        int niter = (cnt + 1) >> 1;       // edges per team (team1 may have 1 fewer)
        int it = 0;
        // depth-2: 4 edges (2 per team) in flight
        for (; it + 2 <= niter; it += 2) {
            int ja = 2 * it + team;                      // always < cnt
            int jx = ja + 2;
            int jcb = min(jx, cnt - 1);
            bool vb = jx < cnt;
            int sa = __shfl_sync(0xffffffffu, myc, ja);
            int sb = __shfl_sync(0xffffffffu, myc, jcb);
            const uint4* pa = (const uint4*)(jb.qkv_src + (size_t)sa * QKVW);
            const uint4* pb = (const uint4*)(jb.qkv_src + (size_t)sb * QKVW);
            uint4 ka = __ldg(pa + 16 + tlane), va = __ldg(pa + 32 + tlane);
            uint4 kb = __ldg(pb + 16 + tlane), vbv = __ldg(pb + 32 + tlane);
            team_edge(ka, va, true, qf, scale, acc, ssum);
            team_edge(kb, vbv, vb, qf, scale, acc, ssum);
        }
        for (; it < niter; it++) {
            int j = 2 * it + team;
            int jc = min(j, cnt - 1);
            bool v_ = j < cnt;
            int s0 = __shfl_sync(0xffffffffu, myc, jc);
            const uint4* p0 = (const uint4*)(jb.qkv_src + (size_t)s0 * QKVW);
            uint4 k0 = __ldg(p0 + 16 + tlane), v0 = __ldg(p0 + 32 + tlane);
            team_edge(k0, v0, v_, qf, scale, acc, ssum);
        }
    }

    // merge the two teams (same tlane across teams holds same output slots)
#pragma unroll
    for (int i = 0; i < 8; i++) acc[i] += __shfl_xor_sync(0xffffffffu, acc[i], 16);
    ssum += __shfl_xor_sync(0xffffffffu, ssum, 16);

    if (team == 0) {
        float inv = 1.0f / (ssum + 1e-16f);
        float* op = jb.agg + (size_t)dst * CHID + tlane * 8;
        *(float4*)(op)     = make_float4(acc[0] * inv, acc[1] * inv, acc[2] * inv, acc[3] * inv);
        *(float4*)(op + 4) = make_float4(acc[4] * inv, acc[5] * inv, acc[6] * inv, acc[7] * inv);
    }
}

// ---------------- final pair scores ----------------
__global__ void __launch_bounds__(256)
pred_kernel(const int* __restrict__ pidx, int P, float* __restrict__ out) {
    int warp = (blockIdx.x * blockDim.x + threadIdx.x) >> 5;
    int lane = threadIdx.x & 31;
    if (warp >= P) return;
    int i = pidx[warp];
    int j = pidx[P + warp];
    const float4* em = (const float4*)(g_Em + (size_t)i * (CHID * CNL));
    const float4* ed = (const float4*)(g_Ed + (size_t)j * (CHID * CNL));
    float4 a0 = em[lane],      b0 = ed[lane];
    float4 a1 = em[32 + lane], b1 = ed[32 + lane];
    float d = a0.x * b0.x + a0.y * b0.y + a0.z * b0.z + a0.w * b0.w
            + a1.x * b1.x + a1.y * b1.y + a1.z * b1.z + a1.w * b1.w;
#pragma unroll
    for (int o = 16; o > 0; o >>= 1) d += __shfl_xor_sync(0xffffffffu, d, o);
    if (lane == 0) out[warp] = d;
}

// ---------------- host driver ----------------
extern "C" void kernel_launch(void* const* d_in, const int* in_sizes, int n_in,
                              void* d_out, int out_size) {
    const float* x1    = (const float*)d_in[0];
    const float* x2    = (const float*)d_in[1];
    const int*   ei12  = (const int*)d_in[2];
    const int*   ei21  = (const int*)d_in[3];
    const int*   pidx  = (const int*)d_in[4];
    const float* Win1  = (const float*)d_in[5];
    const float* bin1  = (const float*)d_in[6];
    const float* Win2  = (const float*)d_in[7];
    const float* bin2  = (const float*)d_in[8];
    const float* Wk    = (const float*)d_in[9];
    const float* bk    = (const float*)d_in[10];
    const float* Wq    = (const float*)d_in[11];
    const float* bq    = (const float*)d_in[12];
    const float* Wv    = (const float*)d_in[13];
    const float* bv    = (const float*)d_in[14];
    const float* Wa    = (const float*)d_in[15];
    const float* ba    = (const float*)d_in[16];
    const float* skip  = (const float*)d_in[17];
    const float* arel  = (const float*)d_in[18];
    const float* mrel  = (const float*)d_in[19];
    const float* prior = (const float*)d_in[20];
    float* out = (float*)d_out;

    const int E = in_sizes[2] / 2;
    const int P = in_sizes[4] / 2;

    float *h1, *h2, *agg1, *agg2, *Em, *Ed, *Wcat, *bcat;
    __half *qkv1, *qkv2;
    int *rp12, *rp21, *src12, *src21;
    cudaGetSymbolAddress((void**)&h1,   g_h1);
    cudaGetSymbolAddress((void**)&h2,   g_h2);
    cudaGetSymbolAddress((void**)&qkv1, g_qkv1);
    cudaGetSymbolAddress((void**)&qkv2, g_qkv2);
    cudaGetSymbolAddress((void**)&agg1, g_agg1);
    cudaGetSymbolAddress((void**)&agg2, g_agg2);
    cudaGetSymbolAddress((void**)&Em,   g_Em);
    cudaGetSymbolAddress((void**)&Ed,   g_Ed);
    cudaGetSymbolAddress((void**)&Wcat, g_Wcat);
    cudaGetSymbolAddress((void**)&bcat, g_bcat);
    cudaGetSymbolAddress((void**)&rp12, g_rp12);
    cudaGetSymbolAddress((void**)&rp21, g_rp21);
    cudaGetSymbolAddress((void**)&src12, g_src12);
    cudaGetSymbolAddress((void**)&src21, g_src21);

    const int WW = CHID * CHID;

    // prep_cat blocks 0-3 build weights; blocks 4+ zero CSR counters
    prep_cat<<<4 + (CN1 + 255) / 256, 256>>>(Wq, bq, Wk, bk, Wv, bv, arel, mrel);
    csr_hist<<<(2 * E + 255) / 256, 256>>>(ei12, ei21, E);
    {
        int shbytes = (CN1 + 1024) * sizeof(int);
        csr_scan<<<2, 1024, shbytes>>>(CN1);
    }
    csr_scatter<<<(2 * E + 255) / 256, 256>>>(ei12, ei21, E);

    // input projections + ReLU (both node types in one launch)
    {
        GJob j0 = { x1, CF_IN, Win1, CHID, bin1, h1, CHID, nullptr, 0, CN1, CF_IN, nullptr, 0, nullptr };
        GJob j1 = { x2, CF_IN, Win2, CHID, bin2, h2, CHID, nullptr, 0, CN2, CF_IN, nullptr, 0, nullptr };
        gemm_tc<<<dim3((CN1 + 127) / 128, 1, 2), 256>>>(j0, j1, 1);
    }

    for (int l = 0; l < CNL; l++) {
        const float* A1 = (l == 0) ? h1 : Em;
        const float* A2 = (l == 0) ? h2 : Ed;
        int lda = (l == 0) ? CHID : CNL * CHID;
        int c0 = l * 2 + 0, c1 = l * 2 + 1;

        {
            GJob j0 = { A1, lda, Wcat + (size_t)c0 * CHID * QKVW, QKVW, bcat + c0 * QKVW,
                        nullptr, 0, qkv1, QKVW, CN1, CHID, nullptr, 0, nullptr };
            GJob j1 = { A2, lda, Wcat + (size_t)c1 * CHID * QKVW, QKVW, bcat + c1 * QKVW,
                        nullptr, 0, qkv2, QKVW, CN2, CHID, nullptr, 0, nullptr };
            gemm_tc<<<dim3((CN1 + 127) / 128, 3, 2), 256>>>(j0, j1, 3);
        }

        {
            AJob a = { rp12, src12, qkv2, qkv1, prior + c0 * CNH, agg2, CN2 };
            AJob b = { rp21, src21, qkv1, qkv2, prior + c1 * CNH, agg1, CN1 };
            int warps = CN1 + CN2;
            attend_csr<<<(warps * 32 + 255) / 256, 256>>>(a, b);
        }

        {
            const float* hold1 = (l == 0) ? h1 : Em;
            const float* hold2 = (l == 0) ? h2 : Ed;
            int ldh = (l == 0) ? CHID : CNL * CHID;
            GJob j0 = { agg1, CHID, Wa + (size_t)c0 * WW, CHID, ba + c0 * CHID,
                        Em + l * CHID, CNL * CHID, nullptr, 0, CN1, CHID, hold1, ldh, skip + c0 };
            GJob j1 = { agg2, CHID, Wa + (size_t)c1 * WW, CHID, ba + c1 * CHID,
                        Ed + l * CHID, CNL * CHID, nullptr, 0, CN2, CHID, hold2, ldh, skip + c1 };
            gemm_tc<<<dim3((CN1 + 127) / 128, 1, 2), 256>>>(j0, j1, 2);
        }
    }

    pred_kernel<<<(P * 32 + 255) / 256, 256>>>(pidx, P, out);
}

// round 13
// speedup vs baseline: 1.5141x; 1.0227x over previous
#include <cuda_runtime.h>
#include <cuda_fp16.h>
#include <math.h>

#define CN1 10000
#define CN2 10000
#define CF_IN 256
#define CHID 128
#define CNH 8
#define CDH 16
#define CNL 2
#define QKVW 384
#define EMAX 480000

// ---------------- scratch (static device globals) ----------------
__device__ float  g_h1[CN1 * CHID];
__device__ float  g_h2[CN2 * CHID];
__device__ __half g_qkv1[CN1 * QKVW];
__device__ __half g_qkv2[CN2 * QKVW];
__device__ float  g_agg1[CN1 * CHID], g_agg2[CN2 * CHID];
__device__ float  g_Em[CN1 * CHID * CNL], g_Ed[CN2 * CHID * CNL];
__device__ float  g_Wcat[CNL * 2 * CHID * QKVW];
__device__ float  g_bcat[CNL * 2 * QKVW];
// CSR scratch
__device__ int g_cnt12[CN2], g_cnt21[CN1];
__device__ int g_rp12[CN2 + 1], g_rp21[CN1 + 1];
__device__ int g_pos12[EMAX], g_pos21[EMAX];
__device__ int g_src12[EMAX], g_src21[EMAX];

// ---------------- helpers ----------------
__device__ __forceinline__ float gelu_f(float x) {
    float x3 = x * x * x;
    return 0.5f * x * (1.0f + tanhf(0.7978845608028654f * (x + 0.044715f * x3)));
}

__device__ __forceinline__ unsigned f2tf(float x) {
    unsigned r;
    asm("cvt.rna.tf32.f32 %0, %1;" : "=r"(r) : "f"(x));
    return r;
}

// ---------------- build packed weights (+ zero CSR counters in extra blocks) ----------------
__global__ void prep_cat(const float* __restrict__ Wq, const float* __restrict__ bq,
                         const float* __restrict__ Wk, const float* __restrict__ bk,
                         const float* __restrict__ Wv, const float* __restrict__ bv,
                         const float* __restrict__ arel, const float* __restrict__ mrel) {
    if (blockIdx.x >= 4) {
        int i = (blockIdx.x - 4) * blockDim.x + threadIdx.x;
        if (i < CN2) g_cnt12[i] = 0;
        if (i < CN1) g_cnt21[i] = 0;
        return;
    }
    int combo = blockIdx.x;
    const int WW = CHID * CHID;
    float* Wcat = g_Wcat + (size_t)combo * CHID * QKVW;
    float* bcat = g_bcat + combo * QKVW;
    int tid = threadIdx.x;
    for (int i = tid; i < CHID * QKVW; i += blockDim.x) {
        int c = i / QKVW, col = i % QKVW;
        float val;
        if (col < 128) {
            val = Wq[(size_t)combo * WW + c * CHID + col];
        } else if (col < 256) {
            int cc = col - 128, h = cc >> 4, e = cc & 15;
            const float* rel = arel + (size_t)combo * CNH * CDH * CDH + h * CDH * CDH;
            float acc = 0.f;
#pragma unroll
            for (int d = 0; d < CDH; d++)
                acc += Wk[(size_t)combo * WW + c * CHID + h * CDH + d] * rel[d * CDH + e];
            val = acc;
        } else {
            int cc = col - 256, h = cc >> 4, e = cc & 15;
            const float* rel = mrel + (size_t)combo * CNH * CDH * CDH + h * CDH * CDH;
            float acc = 0.f;
#pragma unroll
            for (int d = 0; d < CDH; d++)
                acc += Wv[(size_t)combo * WW + c * CHID + h * CDH + d] * rel[d * CDH + e];
            val = acc;
        }
        Wcat[i] = val;
    }
    if (tid < QKVW) {
        int col = tid;
        float val;
        if (col < 128) {
            val = bq[combo * CHID + col];
        } else if (col < 256) {
            int cc = col - 128, h = cc >> 4, e = cc & 15;
            const float* rel = arel + (size_t)combo * CNH * CDH * CDH + h * CDH * CDH;
            float acc = 0.f;
#pragma unroll
            for (int d = 0; d < CDH; d++) acc += bk[combo * CHID + h * CDH + d] * rel[d * CDH + e];
            val = acc;
        } else {
            int cc = col - 256, h = cc >> 4, e = cc & 15;
            const float* rel = mrel + (size_t)combo * CNH * CDH * CDH + h * CDH * CDH;
            float acc = 0.f;
#pragma unroll
            for (int d = 0; d < CDH; d++) acc += bv[combo * CHID + h * CDH + d] * rel[d * CDH + e];
            val = acc;
        }
        bcat[col] = val;
    }
}

// ---------------- CSR build ----------------
// hist also records each edge's slot within its dst bucket -> scatter is atomic-free
__global__ void csr_hist(const int* __restrict__ ei12, const int* __restrict__ ei21, int E) {
    int i = blockIdx.x * blockDim.x + threadIdx.x;
    if (i < E) {
        g_pos12[i] = atomicAdd(&g_cnt12[ei12[E + i]], 1);
    } else if (i < 2 * E) {
        int j = i - E;
        g_pos21[j] = atomicAdd(&g_cnt21[ei21[E + j]], 1);
    }
}

__global__ void __launch_bounds__(1024) csr_scan(int n) {
    int dir = blockIdx.x;
    const int* cnt = dir ? g_cnt21 : g_cnt12;
    int* rp  = dir ? g_rp21 : g_rp12;
    extern __shared__ int sh[];
    int* vals = sh;
    int* sums = sh + n;
    int t = threadIdx.x;
    for (int i = t; i < n; i += 1024) vals[i] = cnt[i];
    __syncthreads();
    int chunk = (n + 1023) / 1024;
    int s0 = t * chunk;
    int local = 0;
    for (int i = 0; i < chunk; i++) if (s0 + i < n) local += vals[s0 + i];
    sums[t] = local;
    __syncthreads();
    for (int off = 1; off < 1024; off <<= 1) {
        int v = (t >= off) ? sums[t - off] : 0;
        __syncthreads();
        sums[t] += v;
        __syncthreads();
    }
    int run = (t == 0) ? 0 : sums[t - 1];
    int total = sums[1023];
    __syncthreads();
    for (int i = 0; i < chunk; i++) if (s0 + i < n) {
        int c = vals[s0 + i];
        vals[s0 + i] = run;
        run += c;
    }
    __syncthreads();
    for (int i = t; i < n; i += 1024) rp[i] = vals[i];
    if (t == 0) rp[n] = total;
}

__global__ void csr_scatter(const int* __restrict__ ei12, const int* __restrict__ ei21, int E) {
    int i = blockIdx.x * blockDim.x + threadIdx.x;
    if (i < E) {
        int dst = ei12[E + i];
        g_src12[g_rp12[dst] + g_pos12[i]] = ei12[i];
    } else if (i < 2 * E) {
        int j = i - E;
        int dst = ei21[E + j];
        g_src21[g_rp21[dst] + g_pos21[j]] = ei21[j];
    }
}

// ---------------- TF32 tensor-core GEMM: two jobs per launch (blockIdx.z) ----------------
struct GJob {
    const float* A; int lda;
    const float* B; int ldb;
    const float* bias;
    float* Cf; int ldcf;
    __half* Ch; int ldch;
    int M, K;
    const float* hold; int ldh;
    const float* skipp;
};

__global__ void __launch_bounds__(256)
gemm_tc(GJob j0, GJob j1, int mode) {
    GJob jb = blockIdx.z ? j1 : j0;
    __shared__ unsigned As[128][36];
    __shared__ unsigned Bs[32][136];

    int tid  = threadIdx.x;
    int warp = tid >> 5;
    int lane = tid & 31;
    int g = lane >> 2;
    int c = lane & 3;
    int warp_m = warp >> 2;
    int warp_n = warp & 3;
    int m0 = blockIdx.x * 128;
    int n0 = blockIdx.y * 128;

    float acc[4][4][4];
#pragma unroll
    for (int mi = 0; mi < 4; mi++)
#pragma unroll
        for (int ni = 0; ni < 4; ni++)
#pragma unroll
            for (int r = 0; r < 4; r++) acc[mi][ni][r] = 0.f;

    for (int k0 = 0; k0 < jb.K; k0 += 32) {
#pragma unroll
        for (int i = 0; i < 4; i++) {
            int lin = tid + i * 256;
            int row = lin >> 3;
            int kc4 = (lin & 7) << 2;
            float4 v = make_float4(0.f, 0.f, 0.f, 0.f);
            int m = m0 + row;
            if (m < jb.M) {
                v = *(const float4*)(jb.A + (size_t)m * jb.lda + k0 + kc4);
                if (mode == 2) {
                    v.x = gelu_f(v.x); v.y = gelu_f(v.y);
                    v.z = gelu_f(v.z); v.w = gelu_f(v.w);
                }
            }
            uint4 t;
            t.x = f2tf(v.x); t.y = f2tf(v.y); t.z = f2tf(v.z); t.w = f2tf(v.w);
            *(uint4*)&As[row][kc4] = t;
        }
#pragma unroll
        for (int i = 0; i < 4; i++) {
            int lin = tid + i * 256;
            int kr  = lin >> 5;
            int nc4 = (lin & 31) << 2;
            float4 v = *(const float4*)(jb.B + (size_t)(k0 + kr) * jb.ldb + n0 + nc4);
            uint4 t;
            t.x = f2tf(v.x); t.y = f2tf(v.y); t.z = f2tf(v.z); t.w = f2tf(v.w);
            *(uint4*)&Bs[kr][nc4] = t;
        }
        __syncthreads();

#pragma unroll
        for (int ks = 0; ks < 4; ks++) {
            int kk = ks * 8;
            unsigned a[4][4];
#pragma unroll
            for (int mi = 0; mi < 4; mi++) {
                int r0 = warp_m * 64 + mi * 16 + g;
                a[mi][0] = As[r0][kk + c];
                a[mi][1] = As[r0 + 8][kk + c];
                a[mi][2] = As[r0][kk + c + 4];
                a[mi][3] = As[r0 + 8][kk + c + 4];
            }
            unsigned b[4][2];
#pragma unroll
            for (int ni = 0; ni < 4; ni++) {
                int nn = warp_n * 32 + ni * 8 + g;
                b[ni][0] = Bs[kk + c][nn];
                b[ni][1] = Bs[kk + c + 4][nn];
            }
#pragma unroll
            for (int mi = 0; mi < 4; mi++)
#pragma unroll
                for (int ni = 0; ni < 4; ni++) {
                    asm volatile(
                        "mma.sync.aligned.m16n8k8.row.col.f32.tf32.tf32.f32 "
                        "{%0,%1,%2,%3}, {%4,%5,%6,%7}, {%8,%9}, {%0,%1,%2,%3};\n"
                        : "+f"(acc[mi][ni][0]), "+f"(acc[mi][ni][1]),
                          "+f"(acc[mi][ni][2]), "+f"(acc[mi][ni][3])
                        : "r"(a[mi][0]), "r"(a[mi][1]), "r"(a[mi][2]), "r"(a[mi][3]),
                          "r"(b[ni][0]), "r"(b[ni][1]));
                }
        }
        __syncthreads();
    }

    float sg = 1.f, sg1 = 0.f;
    if (mode == 2) {
        sg = 1.0f / (1.0f + __expf(-*jb.skipp));
        sg1 = 1.0f - sg;
    }

#pragma unroll
    for (int mi = 0; mi < 4; mi++) {
#pragma unroll
        for (int half = 0; half < 2; half++) {
            int r = m0 + warp_m * 64 + mi * 16 + g + half * 8;
            if (r >= jb.M) continue;
#pragma unroll
            for (int ni = 0; ni < 4; ni++) {
                int n = n0 + warp_n * 32 + ni * 8 + 2 * c;
                float x0 = acc[mi][ni][half * 2 + 0] + jb.bias[n + 0];
                float x1 = acc[mi][ni][half * 2 + 1] + jb.bias[n + 1];
                if (mode == 1) {
                    x0 = fmaxf(x0, 0.f); x1 = fmaxf(x1, 0.f);
                    *(float2*)(jb.Cf + (size_t)r * jb.ldcf + n) = make_float2(x0, x1);
                } else if (mode == 2) {
                    const float* hp = jb.hold + (size_t)r * jb.ldh + n;
                    *(float2*)(jb.Cf + (size_t)r * jb.ldcf + n) =
                        make_float2(sg * x0 + sg1 * hp[0], sg * x1 + sg1 * hp[1]);
                } else {
                    __half2 p = __floats2half2_rn(x0, x1);
                    *(__half2*)(jb.Ch + (size_t)r * jb.ldch + n) = p;
                }
            }
        }
    }
}

// ---------------- CSR attention: warp = 1 dst, two 16-lane teams, half2 dot ----------------
struct AJob {
    const int* rp; const int* col;
    const __half* qkv_dst; const __half* qkv_src;
    const float* prior;
    float* agg;
    int n;
};

// q stays packed as half2[4]; k consumed packed (hfma2 chain); only v unpacked.
__device__ __forceinline__ void team_edge(uint4 kw, uint4 vw, bool valid,
                                          const __half2* qh, float scale,
                                          float* acc, float& ssum) {
    const __half2* kh = (const __half2*)&kw;
    __half2 p = __hmul2(qh[0], kh[0]);
    p = __hfma2(qh[1], kh[1], p);
    p = __hfma2(qh[2], kh[2], p);
    p = __hfma2(qh[3], kh[3], p);
    float2 df = __half22float2(p);
    float d = df.x + df.y;
    d += __shfl_xor_sync(0xffffffffu, d, 1);   // complete 16-dim head dot
    float e = valid ? __expf(d * scale) : 0.f;
    ssum += e;
    const __half2* vh = (const __half2*)&vw;
#pragma unroll
    for (int i = 0; i < 4; i++) {
        float2 vf = __half22float2(vh[i]);
        acc[2 * i]     += e * vf.x;
        acc[2 * i + 1] += e * vf.y;
    }
}

__global__ void __launch_bounds__(256, 4)
attend_csr(AJob a, AJob b) {
    int gw = (blockIdx.x * blockDim.x + threadIdx.x) >> 5;
    int lane = threadIdx.x & 31;
    int tlane = lane & 15;
    int team  = lane >> 4;
    int total = a.n + b.n;
    if (gw >= total) return;
    AJob jb = (gw < a.n) ? a : b;
    int dst = (gw < a.n) ? gw : gw - a.n;

    int start = __ldg(jb.rp + dst);
    int end   = __ldg(jb.rp + dst + 1);

    // q: lane holds halfs [8*tlane, 8*tlane+8) packed as 4x half2
    uint4 qw = __ldg((const uint4*)(jb.qkv_dst + (size_t)dst * QKVW) + tlane);
    __half2 qh[4];
    qh[0] = *(__half2*)&qw.x; qh[1] = *(__half2*)&qw.y;
    qh[2] = *(__half2*)&qw.z; qh[3] = *(__half2*)&qw.w;
    int h = tlane >> 1;
    float scale = __ldg(jb.prior + h) * 0.25f;

    float acc[8];
#pragma unroll
    for (int i = 0; i < 8; i++) acc[i] = 0.f;
    float ssum = 0.f;

    for (int base = start; base < end; base += 32) {
        int myc = (base + lane < end) ? __ldg(jb.col + base + lane) : 0;
        int cnt = min(32, end - base);
        int niter = (cnt + 1) >> 1;
        int it = 0;
        for (; it + 2 <= niter; it += 2) {
            int ja = 2 * it + team;
            int jx = ja + 2;
            int jcb = min(jx, cnt - 1);
            bool vb = jx < cnt;
            int sa = __shfl_sync(0xffffffffu, myc, ja);
            int sb = __shfl_sync(0xffffffffu, myc, jcb);
            const uint4* pa = (const uint4*)(jb.qkv_src + (size_t)sa * QKVW);
            const uint4* pb = (const uint4*)(jb.qkv_src + (size_t)sb * QKVW);
            uint4 ka = __ldg(pa + 16 + tlane), va = __ldg(pa + 32 + tlane);
            uint4 kb = __ldg(pb + 16 + tlane), vbv = __ldg(pb + 32 + tlane);
            team_edge(ka, va, true, qh, scale, acc, ssum);
            team_edge(kb, vbv, vb, qh, scale, acc, ssum);
        }
        for (; it < niter; it++) {
            int j = 2 * it + team;
            int jc = min(j, cnt - 1);
            bool v_ = j < cnt;
            int s0 = __shfl_sync(0xffffffffu, myc, jc);
            const uint4* p0 = (const uint4*)(jb.qkv_src + (size_t)s0 * QKVW);
            uint4 k0 = __ldg(p0 + 16 + tlane), v0 = __ldg(p0 + 32 + tlane);
            team_edge(k0, v0, v_, qh, scale, acc, ssum);
        }
    }

#pragma unroll
    for (int i = 0; i < 8; i++) acc[i] += __shfl_xor_sync(0xffffffffu, acc[i], 16);
    ssum += __shfl_xor_sync(0xffffffffu, ssum, 16);

    if (team == 0) {
        float inv = 1.0f / (ssum + 1e-16f);
        float* op = jb.agg + (size_t)dst * CHID + tlane * 8;
        *(float4*)(op)     = make_float4(acc[0] * inv, acc[1] * inv, acc[2] * inv, acc[3] * inv);
        *(float4*)(op + 4) = make_float4(acc[4] * inv, acc[5] * inv, acc[6] * inv, acc[7] * inv);
    }
}

// ---------------- final pair scores ----------------
__global__ void __launch_bounds__(256)
pred_kernel(const int* __restrict__ pidx, int P, float* __restrict__ out) {
    int warp = (blockIdx.x * blockDim.x + threadIdx.x) >> 5;
    int lane = threadIdx.x & 31;
    if (warp >= P) return;
    int i = pidx[warp];
    int j = pidx[P + warp];
    const float4* em = (const float4*)(g_Em + (size_t)i * (CHID * CNL));
    const float4* ed = (const float4*)(g_Ed + (size_t)j * (CHID * CNL));
    float4 a0 = em[lane],      b0 = ed[lane];
    float4 a1 = em[32 + lane], b1 = ed[32 + lane];
    float d = a0.x * b0.x + a0.y * b0.y + a0.z * b0.z + a0.w * b0.w
            + a1.x * b1.x + a1.y * b1.y + a1.z * b1.z + a1.w * b1.w;
#pragma unroll
    for (int o = 16; o > 0; o >>= 1) d += __shfl_xor_sync(0xffffffffu, d, o);
    if (lane == 0) out[warp] = d;
}

// ---------------- host driver ----------------
extern "C" void kernel_launch(void* const* d_in, const int* in_sizes, int n_in,
                              void* d_out, int out_size) {
    const float* x1    = (const float*)d_in[0];
    const float* x2    = (const float*)d_in[1];
    const int*   ei12  = (const int*)d_in[2];
    const int*   ei21  = (const int*)d_in[3];
    const int*   pidx  = (const int*)d_in[4];
    const float* Win1  = (const float*)d_in[5];
    const float* bin1  = (const float*)d_in[6];
    const float* Win2  = (const float*)d_in[7];
    const float* bin2  = (const float*)d_in[8];
    const float* Wk    = (const float*)d_in[9];
    const float* bk    = (const float*)d_in[10];
    const float* Wq    = (const float*)d_in[11];
    const float* bq    = (const float*)d_in[12];
    const float* Wv    = (const float*)d_in[13];
    const float* bv    = (const float*)d_in[14];
    const float* Wa    = (const float*)d_in[15];
    const float* ba    = (const float*)d_in[16];
    const float* skip  = (const float*)d_in[17];
    const float* arel  = (const float*)d_in[18];
    const float* mrel  = (const float*)d_in[19];
    const float* prior = (const float*)d_in[20];
    float* out = (float*)d_out;

    const int E = in_sizes[2] / 2;
    const int P = in_sizes[4] / 2;

    float *h1, *h2, *agg1, *agg2, *Em, *Ed, *Wcat, *bcat;
    __half *qkv1, *qkv2;
    int *rp12, *rp21, *src12, *src21;
    cudaGetSymbolAddress((void**)&h1,   g_h1);
    cudaGetSymbolAddress((void**)&h2,   g_h2);
    cudaGetSymbolAddress((void**)&qkv1, g_qkv1);
    cudaGetSymbolAddress((void**)&qkv2, g_qkv2);
    cudaGetSymbolAddress((void**)&agg1, g_agg1);
    cudaGetSymbolAddress((void**)&agg2, g_agg2);
    cudaGetSymbolAddress((void**)&Em,   g_Em);
    cudaGetSymbolAddress((void**)&Ed,   g_Ed);
    cudaGetSymbolAddress((void**)&Wcat, g_Wcat);
    cudaGetSymbolAddress((void**)&bcat, g_bcat);
    cudaGetSymbolAddress((void**)&rp12, g_rp12);
    cudaGetSymbolAddress((void**)&rp21, g_rp21);
    cudaGetSymbolAddress((void**)&src12, g_src12);
    cudaGetSymbolAddress((void**)&src21, g_src21);

    const int WW = CHID * CHID;

    prep_cat<<<4 + (CN1 + 255) / 256, 256>>>(Wq, bq, Wk, bk, Wv, bv, arel, mrel);
    csr_hist<<<(2 * E + 255) / 256, 256>>>(ei12, ei21, E);
    {
        int shbytes = (CN1 + 1024) * sizeof(int);
        csr_scan<<<2, 1024, shbytes>>>(CN1);
    }
    csr_scatter<<<(2 * E + 255) / 256, 256>>>(ei12, ei21, E);

    {
        GJob j0 = { x1, CF_IN, Win1, CHID, bin1, h1, CHID, nullptr, 0, CN1, CF_IN, nullptr, 0, nullptr };
        GJob j1 = { x2, CF_IN, Win2, CHID, bin2, h2, CHID, nullptr, 0, CN2, CF_IN, nullptr, 0, nullptr };
        gemm_tc<<<dim3((CN1 + 127) / 128, 1, 2), 256>>>(j0, j1, 1);
    }

    for (int l = 0; l < CNL; l++) {
        const float* A1 = (l == 0) ? h1 : Em;
        const float* A2 = (l == 0) ? h2 : Ed;
        int lda = (l == 0) ? CHID : CNL * CHID;
        int c0 = l * 2 + 0, c1 = l * 2 + 1;

        {
            GJob j0 = { A1, lda, Wcat + (size_t)c0 * CHID * QKVW, QKVW, bcat + c0 * QKVW,
                        nullptr, 0, qkv1, QKVW, CN1, CHID, nullptr, 0, nullptr };
            GJob j1 = { A2, lda, Wcat + (size_t)c1 * CHID * QKVW, QKVW, bcat + c1 * QKVW,
                        nullptr, 0, qkv2, QKVW, CN2, CHID, nullptr, 0, nullptr };
            gemm_tc<<<dim3((CN1 + 127) / 128, 3, 2), 256>>>(j0, j1, 3);
        }

        {
            AJob a = { rp12, src12, qkv2, qkv1, prior + c0 * CNH, agg2, CN2 };
            AJob b = { rp21, src21, qkv1, qkv2, prior + c1 * CNH, agg1, CN1 };
            int warps = CN1 + CN2;
            attend_csr<<<(warps * 32 + 255) / 256, 256>>>(a, b);
        }

        {
            const float* hold1 = (l == 0) ? h1 : Em;
            const float* hold2 = (l == 0) ? h2 : Ed;
            int ldh = (l == 0) ? CHID : CNL * CHID;
            GJob j0 = { agg1, CHID, Wa + (size_t)c0 * WW, CHID, ba + c0 * CHID,
                        Em + l * CHID, CNL * CHID, nullptr, 0, CN1, CHID, hold1, ldh, skip + c0 };
            GJob j1 = { agg2, CHID, Wa + (size_t)c1 * WW, CHID, ba + c1 * CHID,
                        Ed + l * CHID, CNL * CHID, nullptr, 0, CN2, CHID, hold2, ldh, skip + c1 };
            gemm_tc<<<dim3((CN1 + 127) / 128, 1, 2), 256>>>(j0, j1, 2);
        }
    }

    pred_kernel<<<(P * 32 + 255) / 256, 256>>>(pidx, P, out);
}